// round 5
// baseline (speedup 1.0000x reference)
#include <cuda_runtime.h>
#include <cuda_bf16.h>
#include <math.h>
#include <stdint.h>

#define MAXB    262144
#define TILE_M  128
#define THREADS 512
#define EPSF    1e-6f

#define NCHUNK   26
#define CHUNK_U4 2048
#define BUFSZ    32768
#define SA_HI    0
#define SA_LO    65536
#define BUF_OFF  131072
#define SMEM_TOTAL (BUF_OFF + 3*BUFSZ)     // 229376

// ---------------- device globals ----------------
__device__ __align__(128) uint4 g_wimg[NCHUNK * CHUNK_U4];   // b-frag weight image
__device__ float g_c1[256];                                  // b1 + latent @ W1[25:153]
__device__ float g_R[MAXB * 9];                              // polar rotations

// ---------------- helpers ----------------
__device__ __forceinline__ uint32_t smem_to_u32(const void* p) {
    uint32_t a;
    asm("{ .reg .u64 t; cvta.to.shared.u64 t, %1; cvt.u32.u64 %0, t; }" : "=r"(a) : "l"(p));
    return a;
}

__device__ __forceinline__ uint32_t packbf2(float lo, float hi) {
    uint32_t r;
    asm("cvt.rn.bf16x2.f32 %0, %1, %2;" : "=r"(r) : "f"(hi), "f"(lo));
    return r;
}

__device__ __forceinline__ void split2(float a, float b, uint32_t& h, uint32_t& l) {
    h = packbf2(a, b);
    float ha = __uint_as_float(h << 16);
    float hb = __uint_as_float(h & 0xffff0000u);
    l = packbf2(a - ha, b - hb);
}

__device__ __forceinline__ void mma_bf16(float* d, const uint4& a, uint32_t b0, uint32_t b1) {
    asm volatile("mma.sync.aligned.m16n8k16.row.col.f32.bf16.bf16.f32 "
        "{%0,%1,%2,%3}, {%4,%5,%6,%7}, {%8,%9}, {%0,%1,%2,%3};"
        : "+f"(d[0]), "+f"(d[1]), "+f"(d[2]), "+f"(d[3])
        : "r"(a.x), "r"(a.y), "r"(a.z), "r"(a.w), "r"(b0), "r"(b1));
}

__device__ __forceinline__ void cpasync16(uint32_t dst, const void* src) {
    asm volatile("cp.async.cg.shared.global [%0], [%1], 16;" :: "r"(dst), "l"(src));
}
#define CP_COMMIT() asm volatile("cp.async.commit_group;" ::: "memory")
#define CP_WAIT2()  asm volatile("cp.async.wait_group 2;" ::: "memory")
#define CP_WAIT0()  asm volatile("cp.async.wait_group 0;" ::: "memory")

__device__ __forceinline__ float gelu_exact(float x) {
    return 0.5f * x * (1.0f + erff(x * 0.70710678118654752f));
}

// ---------------- prep kernel: weight image + c1 fold ----------------
__global__ void wprep_kernel(const float* __restrict__ W1, const float* __restrict__ W2,
                             const float* __restrict__ W3, const float* __restrict__ W4,
                             const float* __restrict__ W5,
                             const float* __restrict__ emb, const int* __restrict__ traj,
                             const float* __restrict__ b1) {
    if (blockIdx.x == 0) {
        int n = threadIdx.x;               // 256 threads
        const float* lat = emb + traj[0] * 128;
        float s = b1[n];
        #pragma unroll 4
        for (int d = 0; d < 128; ++d)
            s = fmaf(__ldg(lat + d), __ldg(W1 + (25 + d) * 256 + n), s);
        g_c1[n] = s;
    }

    int e = blockIdx.x * blockDim.x + threadIdx.x;
    if (e >= NCHUNK * CHUNK_U4) return;
    int gc = e >> 11, within = e & 2047;
    const float* W; int Kreal, Nreal, ld, kt, nt, lane;
    if (gc == 0) {
        W = W1; Kreal = 25; Nreal = 256; ld = 256;
        kt = within >> 10; int rem = within & 1023; nt = rem >> 5; lane = rem & 31;
    } else if (gc <= 8) {
        W = W2; Kreal = 256; Nreal = 256; ld = 256;
        kt = (gc - 1) * 2 + (within >> 10); int rem = within & 1023; nt = rem >> 5; lane = rem & 31;
    } else if (gc <= 16) {
        W = W3; Kreal = 256; Nreal = 256; ld = 256;
        kt = (gc - 9) * 2 + (within >> 10); int rem = within & 1023; nt = rem >> 5; lane = rem & 31;
    } else if (gc <= 24) {
        W = W4; Kreal = 256; Nreal = 256; ld = 256;
        kt = (gc - 17) * 2 + (within >> 10); int rem = within & 1023; nt = rem >> 5; lane = rem & 31;
    } else {
        if (within >= 1024) { g_wimg[e] = make_uint4(0u, 0u, 0u, 0u); return; }
        W = W5; Kreal = 256; Nreal = 9; ld = 9;
        kt = within >> 6; nt = (within >> 5) & 1; lane = within & 31;
    }
    int q = lane & 3, n = nt * 8 + (lane >> 2);
    int k0 = kt * 16 + 2 * q;
    float v00 = (k0     < Kreal && n < Nreal) ? W[(size_t)(k0    ) * ld + n] : 0.f;
    float v01 = (k0 + 1 < Kreal && n < Nreal) ? W[(size_t)(k0 + 1) * ld + n] : 0.f;
    float v10 = (k0 + 8 < Kreal && n < Nreal) ? W[(size_t)(k0 + 8) * ld + n] : 0.f;
    float v11 = (k0 + 9 < Kreal && n < Nreal) ? W[(size_t)(k0 + 9) * ld + n] : 0.f;
    uint4 o;
    uint32_t h, l;
    split2(v00, v01, h, l); o.x = h; o.z = l;
    split2(v10, v11, h, l); o.y = h; o.w = l;
    g_wimg[e] = o;
}

// ---------------- main kernel ----------------
__global__ void __launch_bounds__(THREADS, 1)
mlp_mma_kernel(const float* __restrict__ Fg, const float* __restrict__ Cg,
               const float* __restrict__ b2, const float* __restrict__ b3,
               const float* __restrict__ b4, const float* __restrict__ b5,
               float* __restrict__ outg, int B)
{
    extern __shared__ __align__(1024) char smem[];
    const uint32_t sbase = smem_to_u32(smem);
    const int tid  = threadIdx.x;
    const int lane = tid & 31;
    const int wid  = tid >> 5;
    const int mb   = wid >> 2;       // m block (32 rows), 0..3
    const int nq   = wid & 3;        // n quarter (64 cols), 0..3
    const int q    = lane & 3;
    const int blockRow = blockIdx.x * TILE_M;

    uint4* sAhi = (uint4*)(smem + SA_HI);
    uint4* sAlo = (uint4*)(smem + SA_LO);
    const uint4* bufs = (const uint4*)(smem + BUF_OFF);

    // issue chunk 0 into slot 0
    {
        const uint4* src = g_wimg;
        uint32_t dst = sbase + BUF_OFF;
        #pragma unroll
        for (int r = 0; r < 4; ++r) {
            int idx = r * 512 + tid;
            cpasync16(dst + idx * 16, src + idx);
        }
        CP_COMMIT();
    }

    // ---------------- front-end (threads 0-127; feats -> slot-2 scratch) -----
    float* feats_s = (float*)(smem + BUF_OFF + 2 * BUFSZ);   // [128][33]
    if (tid < TILE_M) {
        int ig = blockRow + tid; if (ig >= B) ig = B - 1;
        float f[9], r[9];
        #pragma unroll
        for (int k = 0; k < 9; ++k) { f[k] = Fg[(size_t)ig * 9 + k]; r[k] = f[k]; }
        #pragma unroll
        for (int it = 0; it < 5; ++it) {
            float c00 = r[4]*r[8]-r[5]*r[7], c01 = r[5]*r[6]-r[3]*r[8], c02 = r[3]*r[7]-r[4]*r[6];
            float c10 = r[2]*r[7]-r[1]*r[8], c11 = r[0]*r[8]-r[2]*r[6], c12 = r[1]*r[6]-r[0]*r[7];
            float c20 = r[1]*r[5]-r[2]*r[4], c21 = r[2]*r[3]-r[0]*r[5], c22 = r[0]*r[4]-r[1]*r[3];
            float det = r[0]*c00 + r[1]*c01 + r[2]*c02;
            float ad  = fmaxf(fabsf(det), 1e-30f);
            float mu  = rcbrtf(ad);
            float s2  = 0.5f * mu;
            float s3  = 0.5f / (mu * det);
            float n0=s2*r[0]+s3*c00, n1=s2*r[1]+s3*c01, n2=s2*r[2]+s3*c02;
            float n3=s2*r[3]+s3*c10, n4=s2*r[4]+s3*c11, n5=s2*r[5]+s3*c12;
            float n6=s2*r[6]+s3*c20, n7=s2*r[7]+s3*c21, n8=s2*r[8]+s3*c22;
            r[0]=n0;r[1]=n1;r[2]=n2;r[3]=n3;r[4]=n4;r[5]=n5;r[6]=n6;r[7]=n7;r[8]=n8;
        }
        float a00=f[0]*f[0]+f[3]*f[3]+f[6]*f[6];
        float a01=f[0]*f[1]+f[3]*f[4]+f[6]*f[7];
        float a02=f[0]*f[2]+f[3]*f[5]+f[6]*f[8];
        float a11=f[1]*f[1]+f[4]*f[4]+f[7]*f[7];
        float a12=f[1]*f[2]+f[4]*f[5]+f[7]*f[8];
        float a22=f[2]*f[2]+f[5]*f[5]+f[8]*f[8];
        float qv = (a00+a11+a22)*(1.0f/3.0f);
        float d0 = a00-qv, d1 = a11-qv, d2 = a22-qv;
        float p2 = d0*d0+d1*d1+d2*d2+2.0f*(a01*a01+a02*a02+a12*a12);
        float e1,e2,e3;
        if (p2 < 1e-18f) { e1=e2=e3=qv; }
        else {
            float p = sqrtf(p2*(1.0f/6.0f)), invp = 1.0f/p;
            float b00=d0*invp,b11=d1*invp,b22=d2*invp;
            float b01=a01*invp,b02=a02*invp,b12=a12*invp;
            float detB = b00*(b11*b22-b12*b12)-b01*(b01*b22-b12*b02)+b02*(b01*b12-b11*b02);
            float rr = fminf(fmaxf(0.5f*detB,-1.0f),1.0f);
            float phi = acosf(rr)*(1.0f/3.0f);
            e1 = qv+2.0f*p*cosf(phi);
            e3 = qv+2.0f*p*cosf(phi+2.09439510239319549f);
            e2 = 3.0f*qv-e1-e3;
        }
        float detF = f[0]*(f[4]*f[8]-f[5]*f[7]) - f[1]*(f[3]*f[8]-f[5]*f[6]) + f[2]*(f[3]*f[7]-f[4]*f[6]);
        float f00c = fmaxf(f[0], EPSF);
        float ft[32];
        ft[0]=sqrtf(fmaxf(e1,0.f))-1.f; ft[1]=sqrtf(fmaxf(e2,0.f))-1.f; ft[2]=sqrtf(fmaxf(e3,0.f))-1.f;
        ft[3]=a00-1.f; ft[4]=a01; ft[5]=a02;
        ft[6]=a01; ft[7]=a11-1.f; ft[8]=a12;
        ft[9]=a02; ft[10]=a12; ft[11]=a22-1.f;
        ft[12]=detF-1.f; ft[13]=logf(detF)-1.f;
        ft[14]=f00c-1.f; ft[15]=logf(f00c)-1.f;
        #pragma unroll
        for (int j = 0; j < 9; ++j) ft[16+j] = Cg[(size_t)ig*9+j];
        #pragma unroll
        for (int j = 25; j < 32; ++j) ft[j] = 0.0f;
        #pragma unroll
        for (int k = 0; k < 32; ++k) feats_s[tid * 33 + k] = ft[k];
        #pragma unroll
        for (int k = 0; k < 9; ++k) g_R[(size_t)ig * 9 + k] = r[k];
    }
    __syncthreads();

    // ---------------- build L1 A-frags: warp wid builds (mtg=wid>>1, kt=wid&1)
    {
        int mtg = wid >> 1;
        int kt  = wid & 1;
        int r0 = mtg * 16 + (lane >> 2);
        int k0 = kt * 16 + 2 * q;
        uint4 h4, l4; uint32_t hh, ll;
        split2(feats_s[r0*33 + k0],       feats_s[r0*33 + k0 + 1],       hh, ll); h4.x = hh; l4.x = ll;
        split2(feats_s[(r0+8)*33 + k0],   feats_s[(r0+8)*33 + k0 + 1],   hh, ll); h4.y = hh; l4.y = ll;
        split2(feats_s[r0*33 + k0 + 8],   feats_s[r0*33 + k0 + 9],       hh, ll); h4.z = hh; l4.z = ll;
        split2(feats_s[(r0+8)*33 + k0+8], feats_s[(r0+8)*33 + k0 + 9],   hh, ll); h4.w = hh; l4.w = ll;
        sAhi[(mtg * 16 + kt) * 32 + lane] = h4;
        sAlo[(mtg * 16 + kt) * 32 + lane] = l4;
    }
    __syncthreads();

    // issue chunks 1 and 2 (slot-2 scratch now free)
    #pragma unroll
    for (int gg = 1; gg <= 2; ++gg) {
        const uint4* src = g_wimg + (size_t)gg * CHUNK_U4;
        uint32_t dst = sbase + BUF_OFF + gg * BUFSZ;
        #pragma unroll
        for (int r = 0; r < 4; ++r) {
            int idx = r * 512 + tid;
            cpasync16(dst + idx * 16, src + idx);
        }
        CP_COMMIT();
    }

    // ---------------- layer loop --------------------------------------------
    float acc[2][8][4];
    #pragma unroll
    for (int m = 0; m < 2; ++m)
        #pragma unroll
        for (int t = 0; t < 8; ++t)
            #pragma unroll
            for (int j = 0; j < 4; ++j) acc[m][t][j] = 0.0f;

    const float* biasA[4] = {g_c1, b2, b3, b4};

    int g = 0;
    for (int L = 0; L < 4; ++L) {
        const int nc = (L == 0) ? 1 : 8;
        const float* bias = biasA[L];
        for (int c = 0; c < nc; ++c, ++g) {
            CP_WAIT2();
            __syncthreads();
            const uint4* buf = bufs + (g % 3) * CHUNK_U4;
            #pragma unroll
            for (int half = 0; half < 2; ++half) {
                int kt = c * 2 + half;
                uint4 ah0 = sAhi[((mb * 2)     * 16 + kt) * 32 + lane];
                uint4 ah1 = sAhi[((mb * 2 + 1) * 16 + kt) * 32 + lane];
                uint4 al0 = sAlo[((mb * 2)     * 16 + kt) * 32 + lane];
                uint4 al1 = sAlo[((mb * 2 + 1) * 16 + kt) * 32 + lane];
                const uint4* bp = buf + half * 1024 + (nq * 8) * 32 + lane;
                uint4 b = bp[0];
                #pragma unroll
                for (int t = 0; t < 8; ++t) {
                    uint4 bn;
                    if (t < 7) bn = bp[(t + 1) * 32];
                    mma_bf16(acc[0][t], ah0, b.x, b.y);
                    mma_bf16(acc[1][t], ah1, b.x, b.y);
                    mma_bf16(acc[0][t], al0, b.x, b.y);
                    mma_bf16(acc[1][t], al1, b.x, b.y);
                    mma_bf16(acc[0][t], ah0, b.z, b.w);
                    mma_bf16(acc[1][t], ah1, b.z, b.w);
                    b = bn;
                }
            }

            if (c == nc - 1) {
                // layer epilogue: bias + exact GELU + hi/lo split -> A-frags
                #pragma unroll
                for (int m = 0; m < 2; ++m) {
                    int mtg = mb * 2 + m;
                    #pragma unroll
                    for (int tt = 0; tt < 4; ++tt) {
                        float gv[2][4];
                        #pragma unroll
                        for (int u = 0; u < 2; ++u) {
                            int t = 2 * tt + u;
                            float b0  = __ldg(bias + nq * 64 + t * 8 + 2 * q);
                            float b1v = __ldg(bias + nq * 64 + t * 8 + 2 * q + 1);
                            gv[u][0] = gelu_exact(acc[m][t][0] + b0);
                            gv[u][1] = gelu_exact(acc[m][t][1] + b1v);
                            gv[u][2] = gelu_exact(acc[m][t][2] + b0);
                            gv[u][3] = gelu_exact(acc[m][t][3] + b1v);
                            acc[m][t][0] = 0.f; acc[m][t][1] = 0.f;
                            acc[m][t][2] = 0.f; acc[m][t][3] = 0.f;
                        }
                        uint4 h4, l4; uint32_t hh, ll;
                        split2(gv[0][0], gv[0][1], hh, ll); h4.x = hh; l4.x = ll;
                        split2(gv[0][2], gv[0][3], hh, ll); h4.y = hh; l4.y = ll;
                        split2(gv[1][0], gv[1][1], hh, ll); h4.z = hh; l4.z = ll;
                        split2(gv[1][2], gv[1][3], hh, ll); h4.w = hh; l4.w = ll;
                        int kt_out = nq * 4 + tt;
                        sAhi[(mtg * 16 + kt_out) * 32 + lane] = h4;
                        sAlo[(mtg * 16 + kt_out) * 32 + lane] = l4;
                    }
                }
            }
            __syncthreads();          // chunk g reads done + A-frags visible
            if (g + 3 < NCHUNK) {
                const uint4* src = g_wimg + (size_t)(g + 3) * CHUNK_U4;
                uint32_t dst = sbase + BUF_OFF + (g % 3) * BUFSZ;
                #pragma unroll
                for (int r = 0; r < 4; ++r) {
                    int idx = r * 512 + tid;
                    cpasync16(dst + idx * 16, src + idx);
                }
                CP_COMMIT();
            }
        }
    }

    // ---------------- layer 5: [128,256] @ [256,16]; warps with nq<2 ---------
    CP_WAIT0();
    __syncthreads();
    float* plain = (float*)(smem + BUF_OFF);                 // slot 0 reuse, [128][18]
    if (nq < 2) {
        const int nt = nq;
        const uint4* buf = bufs + (25 % 3) * CHUNK_U4;       // chunk 25 -> slot 1
        #pragma unroll
        for (int kt = 0; kt < 16; ++kt) {
            uint4 ah0 = sAhi[((mb * 2)     * 16 + kt) * 32 + lane];
            uint4 ah1 = sAhi[((mb * 2 + 1) * 16 + kt) * 32 + lane];
            uint4 al0 = sAlo[((mb * 2)     * 16 + kt) * 32 + lane];
            uint4 al1 = sAlo[((mb * 2 + 1) * 16 + kt) * 32 + lane];
            uint4 b = buf[kt * 64 + nt * 32 + lane];
            mma_bf16(acc[0][0], ah0, b.x, b.y);
            mma_bf16(acc[1][0], ah1, b.x, b.y);
            mma_bf16(acc[0][0], al0, b.x, b.y);
            mma_bf16(acc[1][0], al1, b.x, b.y);
            mma_bf16(acc[0][0], ah0, b.z, b.w);
            mma_bf16(acc[1][0], ah1, b.z, b.w);
        }
        #pragma unroll
        for (int m = 0; m < 2; ++m) {
            int r0 = (mb * 2 + m) * 16 + (lane >> 2);
            int c0 = nt * 8 + 2 * q;
            plain[r0 * 18 + c0]           = acc[m][0][0];
            plain[r0 * 18 + c0 + 1]       = acc[m][0][1];
            plain[(r0 + 8) * 18 + c0]     = acc[m][0][2];
            plain[(r0 + 8) * 18 + c0 + 1] = acc[m][0][3];
        }
    }
    __syncthreads();

    // ---------------- final epilogue -----------------------------------------
    if (tid < TILE_M) {
        int ig = blockRow + tid;
        if (ig < B) {
            float x[9];
            #pragma unroll
            for (int n = 0; n < 9; ++n) x[n] = plain[tid * 18 + n] + __ldg(b5 + n);
            float xs[9];
            xs[0]=x[0]; xs[4]=x[4]; xs[8]=x[8];
            xs[1]=xs[3]=0.5f*(x[1]+x[3]);
            xs[2]=xs[6]=0.5f*(x[2]+x[6]);
            xs[5]=xs[7]=0.5f*(x[5]+x[7]);
            float R[9], Ff[9], P[9];
            #pragma unroll
            for (int k = 0; k < 9; ++k) R[k]  = g_R[(size_t)ig * 9 + k];
            #pragma unroll
            for (int k = 0; k < 9; ++k) Ff[k] = Fg[(size_t)ig * 9 + k];
            #pragma unroll
            for (int rI = 0; rI < 3; ++rI)
                #pragma unroll
                for (int cI = 0; cI < 3; ++cI)
                    P[rI*3+cI] = R[rI*3+0]*xs[0*3+cI] + R[rI*3+1]*xs[1*3+cI] + R[rI*3+2]*xs[2*3+cI];
            #pragma unroll
            for (int rI = 0; rI < 3; ++rI)
                #pragma unroll
                for (int cI = 0; cI < 3; ++cI)
                    outg[(size_t)ig*9 + rI*3 + cI] =
                        P[rI*3+0]*Ff[cI*3+0] + P[rI*3+1]*Ff[cI*3+1] + P[rI*3+2]*Ff[cI*3+2];
        }
    }
}

// ---------------- launch ----------------
extern "C" void kernel_launch(void* const* d_in, const int* in_sizes, int n_in,
                              void* d_out, int out_size) {
    const float* F    = (const float*)d_in[0];
    const float* C    = (const float*)d_in[1];
    const float* emb  = (const float*)d_in[2];
    const int*   traj = (const int*)  d_in[3];
    const float* W1 = (const float*)d_in[4];
    const float* b1 = (const float*)d_in[5];
    const float* W2 = (const float*)d_in[6];
    const float* b2 = (const float*)d_in[7];
    const float* W3 = (const float*)d_in[8];
    const float* b3 = (const float*)d_in[9];
    const float* W4 = (const float*)d_in[10];
    const float* b4 = (const float*)d_in[11];
    const float* W5 = (const float*)d_in[12];
    const float* b5 = (const float*)d_in[13];
    float* out = (float*)d_out;

    int B = in_sizes[0] / 9;
    if (B > MAXB) B = MAXB;

    wprep_kernel<<<(NCHUNK * CHUNK_U4 + 255) / 256, 256>>>(W1, W2, W3, W4, W5, emb, traj, b1);

    cudaFuncSetAttribute(mlp_mma_kernel, cudaFuncAttributeMaxDynamicSharedMemorySize, SMEM_TOTAL);
    int nblk = (B + TILE_M - 1) / TILE_M;
    mlp_mma_kernel<<<nblk, THREADS, SMEM_TOTAL>>>(F, C, b2, b3, b4, b5, out, B);
}

// round 6
// speedup vs baseline: 1.1823x; 1.1823x over previous
#include <cuda_runtime.h>
#include <cuda_bf16.h>
#include <math.h>
#include <stdint.h>

#define MAXB    262144
#define TILE_M  64
#define THREADS 256
#define EPSF    1e-6f

#define NFINE    51            // 16KB fine chunks, linear 0..50
#define FINE_U4  1024
#define BUFSZ    16384
#define SA_HI    0
#define SA_LO    32768
#define BUF_OFF  65536
#define SMEM_TOTAL (BUF_OFF + 3*BUFSZ)     // 114688

// ---------------- device globals ----------------
__device__ __align__(128) uint4 g_wimg[26 * 2048];   // b-frag weight image (51 fine chunks + pad)
__device__ float g_c1[256];                          // b1 + latent @ W1[25:153]
__device__ float g_R[MAXB * 9];                      // polar rotations

// ---------------- helpers ----------------
__device__ __forceinline__ uint32_t smem_to_u32(const void* p) {
    uint32_t a;
    asm("{ .reg .u64 t; cvta.to.shared.u64 t, %1; cvt.u32.u64 %0, t; }" : "=r"(a) : "l"(p));
    return a;
}

__device__ __forceinline__ uint32_t packbf2(float lo, float hi) {
    uint32_t r;
    asm("cvt.rn.bf16x2.f32 %0, %1, %2;" : "=r"(r) : "f"(hi), "f"(lo));
    return r;
}

__device__ __forceinline__ void split2(float a, float b, uint32_t& h, uint32_t& l) {
    h = packbf2(a, b);
    float ha = __uint_as_float(h << 16);
    float hb = __uint_as_float(h & 0xffff0000u);
    l = packbf2(a - ha, b - hb);
}

__device__ __forceinline__ void mma_bf16(float* d, const uint4& a, uint32_t b0, uint32_t b1) {
    asm volatile("mma.sync.aligned.m16n8k16.row.col.f32.bf16.bf16.f32 "
        "{%0,%1,%2,%3}, {%4,%5,%6,%7}, {%8,%9}, {%0,%1,%2,%3};"
        : "+f"(d[0]), "+f"(d[1]), "+f"(d[2]), "+f"(d[3])
        : "r"(a.x), "r"(a.y), "r"(a.z), "r"(a.w), "r"(b0), "r"(b1));
}

__device__ __forceinline__ void cpasync16(uint32_t dst, const void* src) {
    asm volatile("cp.async.cg.shared.global [%0], [%1], 16;" :: "r"(dst), "l"(src));
}
#define CP_COMMIT() asm volatile("cp.async.commit_group;" ::: "memory")
#define CP_WAIT2()  asm volatile("cp.async.wait_group 2;" ::: "memory")
#define CP_WAIT0()  asm volatile("cp.async.wait_group 0;" ::: "memory")

__device__ __forceinline__ float gelu_exact(float x) {
    return 0.5f * x * (1.0f + erff(x * 0.70710678118654752f));
}

// ---------------- prep kernel: weight image + c1 fold ----------------
__global__ void wprep_kernel(const float* __restrict__ W1, const float* __restrict__ W2,
                             const float* __restrict__ W3, const float* __restrict__ W4,
                             const float* __restrict__ W5,
                             const float* __restrict__ emb, const int* __restrict__ traj,
                             const float* __restrict__ b1) {
    if (blockIdx.x == 0) {
        int n = threadIdx.x;               // 256 threads
        const float* lat = emb + traj[0] * 128;
        float s = b1[n];
        #pragma unroll 4
        for (int d = 0; d < 128; ++d)
            s = fmaf(__ldg(lat + d), __ldg(W1 + (25 + d) * 256 + n), s);
        g_c1[n] = s;
    }

    int e = blockIdx.x * blockDim.x + threadIdx.x;
    if (e >= 26 * 2048) return;
    int gc = e >> 11, within = e & 2047;
    const float* W; int Kreal, Nreal, ld, kt, nt, lane;
    if (gc == 0) {
        W = W1; Kreal = 25; Nreal = 256; ld = 256;
        kt = within >> 10; int rem = within & 1023; nt = rem >> 5; lane = rem & 31;
    } else if (gc <= 8) {
        W = W2; Kreal = 256; Nreal = 256; ld = 256;
        kt = (gc - 1) * 2 + (within >> 10); int rem = within & 1023; nt = rem >> 5; lane = rem & 31;
    } else if (gc <= 16) {
        W = W3; Kreal = 256; Nreal = 256; ld = 256;
        kt = (gc - 9) * 2 + (within >> 10); int rem = within & 1023; nt = rem >> 5; lane = rem & 31;
    } else if (gc <= 24) {
        W = W4; Kreal = 256; Nreal = 256; ld = 256;
        kt = (gc - 17) * 2 + (within >> 10); int rem = within & 1023; nt = rem >> 5; lane = rem & 31;
    } else {
        if (within >= 1024) { g_wimg[e] = make_uint4(0u, 0u, 0u, 0u); return; }
        W = W5; Kreal = 256; Nreal = 9; ld = 9;
        kt = within >> 6; nt = (within >> 5) & 1; lane = within & 31;
    }
    int q = lane & 3, n = nt * 8 + (lane >> 2);
    int k0 = kt * 16 + 2 * q;
    float v00 = (k0     < Kreal && n < Nreal) ? W[(size_t)(k0    ) * ld + n] : 0.f;
    float v01 = (k0 + 1 < Kreal && n < Nreal) ? W[(size_t)(k0 + 1) * ld + n] : 0.f;
    float v10 = (k0 + 8 < Kreal && n < Nreal) ? W[(size_t)(k0 + 8) * ld + n] : 0.f;
    float v11 = (k0 + 9 < Kreal && n < Nreal) ? W[(size_t)(k0 + 9) * ld + n] : 0.f;
    uint4 o;
    uint32_t h, l;
    split2(v00, v01, h, l); o.x = h; o.z = l;
    split2(v10, v11, h, l); o.y = h; o.w = l;
    g_wimg[e] = o;
}

// ---------------- main kernel: 64 rows/CTA, 2 CTAs/SM ----------------
__global__ void __launch_bounds__(THREADS, 2)
mlp_mma_kernel(const float* __restrict__ Fg, const float* __restrict__ Cg,
               const float* __restrict__ b2, const float* __restrict__ b3,
               const float* __restrict__ b4, const float* __restrict__ b5,
               float* __restrict__ outg, int B)
{
    extern __shared__ __align__(1024) char smem[];
    const uint32_t sbase = smem_to_u32(smem);
    const int tid  = threadIdx.x;
    const int lane = tid & 31;
    const int wid  = tid >> 5;
    const int mb   = wid >> 2;       // m block (32 rows), 0..1
    const int nh   = wid & 3;        // n quarter (64 cols), 0..3
    const int q    = lane & 3;
    const int blockRow = blockIdx.x * TILE_M;

    uint4* sAhi = (uint4*)(smem + SA_HI);
    uint4* sAlo = (uint4*)(smem + SA_LO);
    const uint4* bufs = (const uint4*)(smem + BUF_OFF);

    // issue fine chunks 0,1 into slots 0,1 (1024 u4 each; 4 per thread)
    #pragma unroll
    for (int gg = 0; gg < 2; ++gg) {
        const uint4* src = g_wimg + (size_t)gg * FINE_U4;
        uint32_t dst = sbase + BUF_OFF + gg * BUFSZ;
        #pragma unroll
        for (int r = 0; r < 4; ++r) {
            int idx = r * 256 + tid;
            cpasync16(dst + idx * 16, src + idx);
        }
        CP_COMMIT();
    }

    // ---------------- front-end (threads 0-63; feats -> slot-2 scratch) ------
    float* feats_s = (float*)(smem + BUF_OFF + 2 * BUFSZ);   // [64][33]
    if (tid < TILE_M) {
        int ig = blockRow + tid; if (ig >= B) ig = B - 1;
        float f[9], r[9];
        #pragma unroll
        for (int k = 0; k < 9; ++k) { f[k] = Fg[(size_t)ig * 9 + k]; r[k] = f[k]; }
        #pragma unroll
        for (int it = 0; it < 5; ++it) {
            float c00 = r[4]*r[8]-r[5]*r[7], c01 = r[5]*r[6]-r[3]*r[8], c02 = r[3]*r[7]-r[4]*r[6];
            float c10 = r[2]*r[7]-r[1]*r[8], c11 = r[0]*r[8]-r[2]*r[6], c12 = r[1]*r[6]-r[0]*r[7];
            float c20 = r[1]*r[5]-r[2]*r[4], c21 = r[2]*r[3]-r[0]*r[5], c22 = r[0]*r[4]-r[1]*r[3];
            float det = r[0]*c00 + r[1]*c01 + r[2]*c02;
            float ad  = fmaxf(fabsf(det), 1e-30f);
            float mu  = rcbrtf(ad);
            float s2  = 0.5f * mu;
            float s3  = 0.5f / (mu * det);
            float n0=s2*r[0]+s3*c00, n1=s2*r[1]+s3*c01, n2=s2*r[2]+s3*c02;
            float n3=s2*r[3]+s3*c10, n4=s2*r[4]+s3*c11, n5=s2*r[5]+s3*c12;
            float n6=s2*r[6]+s3*c20, n7=s2*r[7]+s3*c21, n8=s2*r[8]+s3*c22;
            r[0]=n0;r[1]=n1;r[2]=n2;r[3]=n3;r[4]=n4;r[5]=n5;r[6]=n6;r[7]=n7;r[8]=n8;
        }
        float a00=f[0]*f[0]+f[3]*f[3]+f[6]*f[6];
        float a01=f[0]*f[1]+f[3]*f[4]+f[6]*f[7];
        float a02=f[0]*f[2]+f[3]*f[5]+f[6]*f[8];
        float a11=f[1]*f[1]+f[4]*f[4]+f[7]*f[7];
        float a12=f[1]*f[2]+f[4]*f[5]+f[7]*f[8];
        float a22=f[2]*f[2]+f[5]*f[5]+f[8]*f[8];
        float qv = (a00+a11+a22)*(1.0f/3.0f);
        float d0 = a00-qv, d1 = a11-qv, d2 = a22-qv;
        float p2 = d0*d0+d1*d1+d2*d2+2.0f*(a01*a01+a02*a02+a12*a12);
        float e1,e2,e3;
        if (p2 < 1e-18f) { e1=e2=e3=qv; }
        else {
            float p = sqrtf(p2*(1.0f/6.0f)), invp = 1.0f/p;
            float b00=d0*invp,b11=d1*invp,b22=d2*invp;
            float b01=a01*invp,b02=a02*invp,b12=a12*invp;
            float detB = b00*(b11*b22-b12*b12)-b01*(b01*b22-b12*b02)+b02*(b01*b12-b11*b02);
            float rr = fminf(fmaxf(0.5f*detB,-1.0f),1.0f);
            float phi = acosf(rr)*(1.0f/3.0f);
            e1 = qv+2.0f*p*cosf(phi);
            e3 = qv+2.0f*p*cosf(phi+2.09439510239319549f);
            e2 = 3.0f*qv-e1-e3;
        }
        float detF = f[0]*(f[4]*f[8]-f[5]*f[7]) - f[1]*(f[3]*f[8]-f[5]*f[6]) + f[2]*(f[3]*f[7]-f[4]*f[6]);
        float f00c = fmaxf(f[0], EPSF);
        float ft[32];
        ft[0]=sqrtf(fmaxf(e1,0.f))-1.f; ft[1]=sqrtf(fmaxf(e2,0.f))-1.f; ft[2]=sqrtf(fmaxf(e3,0.f))-1.f;
        ft[3]=a00-1.f; ft[4]=a01; ft[5]=a02;
        ft[6]=a01; ft[7]=a11-1.f; ft[8]=a12;
        ft[9]=a02; ft[10]=a12; ft[11]=a22-1.f;
        ft[12]=detF-1.f; ft[13]=logf(detF)-1.f;
        ft[14]=f00c-1.f; ft[15]=logf(f00c)-1.f;
        #pragma unroll
        for (int j = 0; j < 9; ++j) ft[16+j] = Cg[(size_t)ig*9+j];
        #pragma unroll
        for (int j = 25; j < 32; ++j) ft[j] = 0.0f;
        #pragma unroll
        for (int k = 0; k < 32; ++k) feats_s[tid * 33 + k] = ft[k];
        #pragma unroll
        for (int k = 0; k < 9; ++k) g_R[(size_t)ig * 9 + k] = r[k];
    }
    __syncthreads();

    // ---------------- build L1 A-frags: warp wid -> (mtg=wid>>1, kt=wid&1) ---
    {
        int mtg = wid >> 1;              // 0..3 (16-row groups)
        int kt  = wid & 1;               // 0..1
        int r0 = mtg * 16 + (lane >> 2);
        int k0 = kt * 16 + 2 * q;
        uint4 h4, l4; uint32_t hh, ll;
        split2(feats_s[r0*33 + k0],       feats_s[r0*33 + k0 + 1],       hh, ll); h4.x = hh; l4.x = ll;
        split2(feats_s[(r0+8)*33 + k0],   feats_s[(r0+8)*33 + k0 + 1],   hh, ll); h4.y = hh; l4.y = ll;
        split2(feats_s[r0*33 + k0 + 8],   feats_s[r0*33 + k0 + 9],       hh, ll); h4.z = hh; l4.z = ll;
        split2(feats_s[(r0+8)*33 + k0+8], feats_s[(r0+8)*33 + k0 + 9],   hh, ll); h4.w = hh; l4.w = ll;
        sAhi[(mtg * 16 + kt) * 32 + lane] = h4;
        sAlo[(mtg * 16 + kt) * 32 + lane] = l4;
    }
    __syncthreads();

    // issue chunk 2 (slot-2 scratch now free)
    {
        const uint4* src = g_wimg + (size_t)2 * FINE_U4;
        uint32_t dst = sbase + BUF_OFF + 2 * BUFSZ;
        #pragma unroll
        for (int r = 0; r < 4; ++r) {
            int idx = r * 256 + tid;
            cpasync16(dst + idx * 16, src + idx);
        }
        CP_COMMIT();
    }

    // ---------------- layer loop (50 fine chunks, one kt each) ---------------
    float acc[2][8][4];
    #pragma unroll
    for (int m = 0; m < 2; ++m)
        #pragma unroll
        for (int t = 0; t < 8; ++t)
            #pragma unroll
            for (int j = 0; j < 4; ++j) acc[m][t][j] = 0.0f;

    const float* biasA[4] = {g_c1, b2, b3, b4};

    int g = 0;
    for (int L = 0; L < 4; ++L) {
        const int nc = (L == 0) ? 2 : 16;       // kt steps this layer
        const float* bias = biasA[L];
        for (int kt = 0; kt < nc; ++kt, ++g) {
            CP_WAIT2();
            __syncthreads();
            const uint4* buf = bufs + (g % 3) * FINE_U4;
            {
                uint4 ah0 = sAhi[((mb * 2)     * 16 + kt) * 32 + lane];
                uint4 ah1 = sAhi[((mb * 2 + 1) * 16 + kt) * 32 + lane];
                uint4 al0 = sAlo[((mb * 2)     * 16 + kt) * 32 + lane];
                uint4 al1 = sAlo[((mb * 2 + 1) * 16 + kt) * 32 + lane];
                const uint4* bp = buf + (nh * 8) * 32 + lane;
                #pragma unroll
                for (int t = 0; t < 8; ++t) {
                    uint4 b = bp[t * 32];
                    mma_bf16(acc[0][t], ah0, b.x, b.y);
                    mma_bf16(acc[1][t], ah1, b.x, b.y);
                    mma_bf16(acc[0][t], al0, b.x, b.y);
                    mma_bf16(acc[1][t], al1, b.x, b.y);
                    mma_bf16(acc[0][t], ah0, b.z, b.w);
                    mma_bf16(acc[1][t], ah1, b.z, b.w);
                }
            }

            if (kt == nc - 1) {
                // layer epilogue: bias + exact GELU + hi/lo split -> A-frags
                #pragma unroll
                for (int m = 0; m < 2; ++m) {
                    int mtg = mb * 2 + m;
                    #pragma unroll
                    for (int tt = 0; tt < 4; ++tt) {
                        float gv[2][4];
                        #pragma unroll
                        for (int u = 0; u < 2; ++u) {
                            int t = 2 * tt + u;
                            float b0  = __ldg(bias + nh * 64 + t * 8 + 2 * q);
                            float b1v = __ldg(bias + nh * 64 + t * 8 + 2 * q + 1);
                            gv[u][0] = gelu_exact(acc[m][t][0] + b0);
                            gv[u][1] = gelu_exact(acc[m][t][1] + b1v);
                            gv[u][2] = gelu_exact(acc[m][t][2] + b0);
                            gv[u][3] = gelu_exact(acc[m][t][3] + b1v);
                            acc[m][t][0] = 0.f; acc[m][t][1] = 0.f;
                            acc[m][t][2] = 0.f; acc[m][t][3] = 0.f;
                        }
                        uint4 h4, l4; uint32_t hh, ll;
                        split2(gv[0][0], gv[0][1], hh, ll); h4.x = hh; l4.x = ll;
                        split2(gv[0][2], gv[0][3], hh, ll); h4.y = hh; l4.y = ll;
                        split2(gv[1][0], gv[1][1], hh, ll); h4.z = hh; l4.z = ll;
                        split2(gv[1][2], gv[1][3], hh, ll); h4.w = hh; l4.w = ll;
                        int kt_out = nh * 4 + tt;
                        sAhi[(mtg * 16 + kt_out) * 32 + lane] = h4;
                        sAlo[(mtg * 16 + kt_out) * 32 + lane] = l4;
                    }
                }
            }
            __syncthreads();          // chunk g reads done + A-frags visible
            if (g + 3 < NFINE) {
                const uint4* src = g_wimg + (size_t)(g + 3) * FINE_U4;
                uint32_t dst = sbase + BUF_OFF + (g % 3) * BUFSZ;
                #pragma unroll
                for (int r = 0; r < 4; ++r) {
                    int idx = r * 256 + tid;
                    cpasync16(dst + idx * 16, src + idx);
                }
                CP_COMMIT();
            }
        }
    }

    // ---------------- layer 5: [64,256] @ [256,16]; warps with nh<2 ----------
    CP_WAIT0();
    __syncthreads();
    float* plain = (float*)(smem + BUF_OFF);                 // slot 0 reuse, [64][18]
    if (nh < 2) {
        const int nt = nh;
        const uint4* buf = bufs + (50 % 3) * FINE_U4;        // chunk 50 -> slot 2
        #pragma unroll
        for (int kt = 0; kt < 16; ++kt) {
            uint4 ah0 = sAhi[((mb * 2)     * 16 + kt) * 32 + lane];
            uint4 ah1 = sAhi[((mb * 2 + 1) * 16 + kt) * 32 + lane];
            uint4 al0 = sAlo[((mb * 2)     * 16 + kt) * 32 + lane];
            uint4 al1 = sAlo[((mb * 2 + 1) * 16 + kt) * 32 + lane];
            uint4 b = buf[kt * 64 + nt * 32 + lane];
            mma_bf16(acc[0][0], ah0, b.x, b.y);
            mma_bf16(acc[1][0], ah1, b.x, b.y);
            mma_bf16(acc[0][0], al0, b.x, b.y);
            mma_bf16(acc[1][0], al1, b.x, b.y);
            mma_bf16(acc[0][0], ah0, b.z, b.w);
            mma_bf16(acc[1][0], ah1, b.z, b.w);
        }
        #pragma unroll
        for (int m = 0; m < 2; ++m) {
            int r0 = (mb * 2 + m) * 16 + (lane >> 2);
            int c0 = nt * 8 + 2 * q;
            plain[r0 * 18 + c0]           = acc[m][0][0];
            plain[r0 * 18 + c0 + 1]       = acc[m][0][1];
            plain[(r0 + 8) * 18 + c0]     = acc[m][0][2];
            plain[(r0 + 8) * 18 + c0 + 1] = acc[m][0][3];
        }
    }
    __syncthreads();

    // ---------------- final epilogue -----------------------------------------
    if (tid < TILE_M) {
        int ig = blockRow + tid;
        if (ig < B) {
            float x[9];
            #pragma unroll
            for (int n = 0; n < 9; ++n) x[n] = plain[tid * 18 + n] + __ldg(b5 + n);
            float xs[9];
            xs[0]=x[0]; xs[4]=x[4]; xs[8]=x[8];
            xs[1]=xs[3]=0.5f*(x[1]+x[3]);
            xs[2]=xs[6]=0.5f*(x[2]+x[6]);
            xs[5]=xs[7]=0.5f*(x[5]+x[7]);
            float R[9], Ff[9], P[9];
            #pragma unroll
            for (int k = 0; k < 9; ++k) R[k]  = g_R[(size_t)ig * 9 + k];
            #pragma unroll
            for (int k = 0; k < 9; ++k) Ff[k] = Fg[(size_t)ig * 9 + k];
            #pragma unroll
            for (int rI = 0; rI < 3; ++rI)
                #pragma unroll
                for (int cI = 0; cI < 3; ++cI)
                    P[rI*3+cI] = R[rI*3+0]*xs[0*3+cI] + R[rI*3+1]*xs[1*3+cI] + R[rI*3+2]*xs[2*3+cI];
            #pragma unroll
            for (int rI = 0; rI < 3; ++rI)
                #pragma unroll
                for (int cI = 0; cI < 3; ++cI)
                    outg[(size_t)ig*9 + rI*3 + cI] =
                        P[rI*3+0]*Ff[cI*3+0] + P[rI*3+1]*Ff[cI*3+1] + P[rI*3+2]*Ff[cI*3+2];
        }
    }
}

// ---------------- launch ----------------
extern "C" void kernel_launch(void* const* d_in, const int* in_sizes, int n_in,
                              void* d_out, int out_size) {
    const float* F    = (const float*)d_in[0];
    const float* C    = (const float*)d_in[1];
    const float* emb  = (const float*)d_in[2];
    const int*   traj = (const int*)  d_in[3];
    const float* W1 = (const float*)d_in[4];
    const float* b1 = (const float*)d_in[5];
    const float* W2 = (const float*)d_in[6];
    const float* b2 = (const float*)d_in[7];
    const float* W3 = (const float*)d_in[8];
    const float* b3 = (const float*)d_in[9];
    const float* W4 = (const float*)d_in[10];
    const float* b4 = (const float*)d_in[11];
    const float* W5 = (const float*)d_in[12];
    const float* b5 = (const float*)d_in[13];
    float* out = (float*)d_out;

    int B = in_sizes[0] / 9;
    if (B > MAXB) B = MAXB;

    wprep_kernel<<<(26 * 2048 + 255) / 256, 256>>>(W1, W2, W3, W4, W5, emb, traj, b1);

    cudaFuncSetAttribute(mlp_mma_kernel, cudaFuncAttributeMaxDynamicSharedMemorySize, SMEM_TOTAL);
    int nblk = (B + TILE_M - 1) / TILE_M;
    mlp_mma_kernel<<<nblk, THREADS, SMEM_TOTAL>>>(F, C, b2, b3, b4, b5, out, B);
}

// round 8
// speedup vs baseline: 1.2012x; 1.0160x over previous
#include <cuda_runtime.h>
#include <cuda_bf16.h>
#include <math.h>
#include <stdint.h>

#define MAXB    262144
#define TILE_M  64
#define THREADS 256
#define EPSF    1e-6f

#define NFINE    51            // 16KB fine chunks, linear 0..50
#define FINE_U4  1024
#define BUFSZ    16384
#define SA_HI    0
#define SA_LO    32768
#define BUF_OFF  65536
#define SMEM_TOTAL (BUF_OFF + 3*BUFSZ)     // 114688 -> 2 CTAs/SM

// ---------------- device globals ----------------
__device__ __align__(128) uint4 g_wimg[26 * 2048];   // b-frag weight image (51 fine chunks + pad)
__device__ float g_c1[256];                          // b1 + latent @ W1[25:153]
__device__ float g_R[MAXB * 9];                      // polar rotations

// ---------------- helpers ----------------
__device__ __forceinline__ uint32_t smem_to_u32(const void* p) {
    uint32_t a;
    asm("{ .reg .u64 t; cvta.to.shared.u64 t, %1; cvt.u32.u64 %0, t; }" : "=r"(a) : "l"(p));
    return a;
}

__device__ __forceinline__ uint32_t packbf2(float lo, float hi) {
    uint32_t r;
    asm("cvt.rn.bf16x2.f32 %0, %1, %2;" : "=r"(r) : "f"(hi), "f"(lo));
    return r;
}

__device__ __forceinline__ void split2(float a, float b, uint32_t& h, uint32_t& l) {
    h = packbf2(a, b);
    float ha = __uint_as_float(h << 16);
    float hb = __uint_as_float(h & 0xffff0000u);
    l = packbf2(a - ha, b - hb);
}

__device__ __forceinline__ void mma_bf16(float* d, const uint4& a, uint32_t b0, uint32_t b1) {
    asm volatile("mma.sync.aligned.m16n8k16.row.col.f32.bf16.bf16.f32 "
        "{%0,%1,%2,%3}, {%4,%5,%6,%7}, {%8,%9}, {%0,%1,%2,%3};"
        : "+f"(d[0]), "+f"(d[1]), "+f"(d[2]), "+f"(d[3])
        : "r"(a.x), "r"(a.y), "r"(a.z), "r"(a.w), "r"(b0), "r"(b1));
}

__device__ __forceinline__ void cpasync16(uint32_t dst, const void* src) {
    asm volatile("cp.async.cg.shared.global [%0], [%1], 16;" :: "r"(dst), "l"(src));
}
#define CP_COMMIT() asm volatile("cp.async.commit_group;" ::: "memory")
#define CP_WAIT2()  asm volatile("cp.async.wait_group 2;" ::: "memory")
#define CP_WAIT0()  asm volatile("cp.async.wait_group 0;" ::: "memory")

__device__ __forceinline__ float gelu_exact(float x) {
    return 0.5f * x * (1.0f + erff(x * 0.70710678118654752f));
}

// ---------------- prep kernel: weight image + c1 fold ----------------
__global__ void wprep_kernel(const float* __restrict__ W1, const float* __restrict__ W2,
                             const float* __restrict__ W3, const float* __restrict__ W4,
                             const float* __restrict__ W5,
                             const float* __restrict__ emb, const int* __restrict__ traj,
                             const float* __restrict__ b1) {
    if (blockIdx.x == 0) {
        int n = threadIdx.x;               // 256 threads
        const float* lat = emb + traj[0] * 128;
        float s = b1[n];
        #pragma unroll 4
        for (int d = 0; d < 128; ++d)
            s = fmaf(__ldg(lat + d), __ldg(W1 + (25 + d) * 256 + n), s);
        g_c1[n] = s;
    }

    int e = blockIdx.x * blockDim.x + threadIdx.x;
    if (e >= 26 * 2048) return;
    int gc = e >> 11, within = e & 2047;
    const float* W; int Kreal, Nreal, ld, kt, nt, lane;
    if (gc == 0) {
        W = W1; Kreal = 25; Nreal = 256; ld = 256;
        kt = within >> 10; int rem = within & 1023; nt = rem >> 5; lane = rem & 31;
    } else if (gc <= 8) {
        W = W2; Kreal = 256; Nreal = 256; ld = 256;
        kt = (gc - 1) * 2 + (within >> 10); int rem = within & 1023; nt = rem >> 5; lane = rem & 31;
    } else if (gc <= 16) {
        W = W3; Kreal = 256; Nreal = 256; ld = 256;
        kt = (gc - 9) * 2 + (within >> 10); int rem = within & 1023; nt = rem >> 5; lane = rem & 31;
    } else if (gc <= 24) {
        W = W4; Kreal = 256; Nreal = 256; ld = 256;
        kt = (gc - 17) * 2 + (within >> 10); int rem = within & 1023; nt = rem >> 5; lane = rem & 31;
    } else {
        if (within >= 1024) { g_wimg[e] = make_uint4(0u, 0u, 0u, 0u); return; }
        W = W5; Kreal = 256; Nreal = 9; ld = 9;
        kt = within >> 6; nt = (within >> 5) & 1; lane = within & 31;
    }
    int q = lane & 3, n = nt * 8 + (lane >> 2);
    int k0 = kt * 16 + 2 * q;
    float v00 = (k0     < Kreal && n < Nreal) ? W[(size_t)(k0    ) * ld + n] : 0.f;
    float v01 = (k0 + 1 < Kreal && n < Nreal) ? W[(size_t)(k0 + 1) * ld + n] : 0.f;
    float v10 = (k0 + 8 < Kreal && n < Nreal) ? W[(size_t)(k0 + 8) * ld + n] : 0.f;
    float v11 = (k0 + 9 < Kreal && n < Nreal) ? W[(size_t)(k0 + 9) * ld + n] : 0.f;
    uint4 o;
    uint32_t h, l;
    split2(v00, v01, h, l); o.x = h; o.z = l;
    split2(v10, v11, h, l); o.y = h; o.w = l;
    g_wimg[e] = o;
}

// ---------------- main kernel: 64 rows/CTA, 2 CTAs/SM, 1 barrier/chunk ------
__global__ void __launch_bounds__(THREADS, 2)
mlp_mma_kernel(const float* __restrict__ Fg, const float* __restrict__ Cg,
               const float* __restrict__ b2, const float* __restrict__ b3,
               const float* __restrict__ b4, const float* __restrict__ b5,
               float* __restrict__ outg, int B)
{
    extern __shared__ __align__(1024) char smem[];
    const uint32_t sbase = smem_to_u32(smem);
    const int tid  = threadIdx.x;
    const int lane = tid & 31;
    const int wid  = tid >> 5;
    const int mb   = wid >> 2;       // m block (32 rows), 0..1
    const int nh   = wid & 3;        // n quarter (64 cols), 0..3
    const int q    = lane & 3;
    const int blockRow = blockIdx.x * TILE_M;

    uint4* sAhi = (uint4*)(smem + SA_HI);
    uint4* sAlo = (uint4*)(smem + SA_LO);
    const uint4* bufs = (const uint4*)(smem + BUF_OFF);

    // issue fine chunks 0,1 into slots 0,1
    #pragma unroll
    for (int gg = 0; gg < 2; ++gg) {
        const uint4* src = g_wimg + (size_t)gg * FINE_U4;
        uint32_t dst = sbase + BUF_OFF + gg * BUFSZ;
        #pragma unroll
        for (int r = 0; r < 4; ++r) {
            int idx = r * 256 + tid;
            cpasync16(dst + idx * 16, src + idx);
        }
        CP_COMMIT();
    }

    // ---------------- front-end (threads 0-63; feats -> slot-2 scratch) ------
    float* feats_s = (float*)(smem + BUF_OFF + 2 * BUFSZ);   // [64][33]
    if (tid < TILE_M) {
        int ig = blockRow + tid; if (ig >= B) ig = B - 1;
        float f[9], r[9];
        #pragma unroll
        for (int k = 0; k < 9; ++k) { f[k] = Fg[(size_t)ig * 9 + k]; r[k] = f[k]; }
        #pragma unroll
        for (int it = 0; it < 5; ++it) {
            float c00 = r[4]*r[8]-r[5]*r[7], c01 = r[5]*r[6]-r[3]*r[8], c02 = r[3]*r[7]-r[4]*r[6];
            float c10 = r[2]*r[7]-r[1]*r[8], c11 = r[0]*r[8]-r[2]*r[6], c12 = r[1]*r[6]-r[0]*r[7];
            float c20 = r[1]*r[5]-r[2]*r[4], c21 = r[2]*r[3]-r[0]*r[5], c22 = r[0]*r[4]-r[1]*r[3];
            float det = r[0]*c00 + r[1]*c01 + r[2]*c02;
            float ad  = fmaxf(fabsf(det), 1e-30f);
            float mu  = rcbrtf(ad);
            float s2  = 0.5f * mu;
            float s3  = 0.5f / (mu * det);
            float n0=s2*r[0]+s3*c00, n1=s2*r[1]+s3*c01, n2=s2*r[2]+s3*c02;
            float n3=s2*r[3]+s3*c10, n4=s2*r[4]+s3*c11, n5=s2*r[5]+s3*c12;
            float n6=s2*r[6]+s3*c20, n7=s2*r[7]+s3*c21, n8=s2*r[8]+s3*c22;
            r[0]=n0;r[1]=n1;r[2]=n2;r[3]=n3;r[4]=n4;r[5]=n5;r[6]=n6;r[7]=n7;r[8]=n8;
        }
        float a00=f[0]*f[0]+f[3]*f[3]+f[6]*f[6];
        float a01=f[0]*f[1]+f[3]*f[4]+f[6]*f[7];
        float a02=f[0]*f[2]+f[3]*f[5]+f[6]*f[8];
        float a11=f[1]*f[1]+f[4]*f[4]+f[7]*f[7];
        float a12=f[1]*f[2]+f[4]*f[5]+f[7]*f[8];
        float a22=f[2]*f[2]+f[5]*f[5]+f[8]*f[8];
        float qv = (a00+a11+a22)*(1.0f/3.0f);
        float d0 = a00-qv, d1 = a11-qv, d2 = a22-qv;
        float p2 = d0*d0+d1*d1+d2*d2+2.0f*(a01*a01+a02*a02+a12*a12);
        float e1,e2,e3;
        if (p2 < 1e-18f) { e1=e2=e3=qv; }
        else {
            float p = sqrtf(p2*(1.0f/6.0f)), invp = 1.0f/p;
            float b00=d0*invp,b11=d1*invp,b22=d2*invp;
            float b01=a01*invp,b02=a02*invp,b12=a12*invp;
            float detB = b00*(b11*b22-b12*b12)-b01*(b01*b22-b12*b02)+b02*(b01*b12-b11*b02);
            float rr = fminf(fmaxf(0.5f*detB,-1.0f),1.0f);
            float phi = acosf(rr)*(1.0f/3.0f);
            e1 = qv+2.0f*p*cosf(phi);
            e3 = qv+2.0f*p*cosf(phi+2.09439510239319549f);
            e2 = 3.0f*qv-e1-e3;
        }
        float detF = f[0]*(f[4]*f[8]-f[5]*f[7]) - f[1]*(f[3]*f[8]-f[5]*f[6]) + f[2]*(f[3]*f[7]-f[4]*f[6]);
        float f00c = fmaxf(f[0], EPSF);
        float ft[32];
        ft[0]=sqrtf(fmaxf(e1,0.f))-1.f; ft[1]=sqrtf(fmaxf(e2,0.f))-1.f; ft[2]=sqrtf(fmaxf(e3,0.f))-1.f;
        ft[3]=a00-1.f; ft[4]=a01; ft[5]=a02;
        ft[6]=a01; ft[7]=a11-1.f; ft[8]=a12;
        ft[9]=a02; ft[10]=a12; ft[11]=a22-1.f;
        ft[12]=detF-1.f; ft[13]=logf(detF)-1.f;
        ft[14]=f00c-1.f; ft[15]=logf(f00c)-1.f;
        #pragma unroll
        for (int j = 0; j < 9; ++j) ft[16+j] = Cg[(size_t)ig*9+j];
        #pragma unroll
        for (int j = 25; j < 32; ++j) ft[j] = 0.0f;
        #pragma unroll
        for (int k = 0; k < 32; ++k) feats_s[tid * 33 + k] = ft[k];
        #pragma unroll
        for (int k = 0; k < 9; ++k) g_R[(size_t)ig * 9 + k] = r[k];
    }
    __syncthreads();

    // ---------------- build L1 A-frags: warp wid -> (mtg=wid>>1, kt=wid&1) ---
    {
        int mtg = wid >> 1;              // 0..3 (16-row groups)
        int kt  = wid & 1;               // 0..1
        int r0 = mtg * 16 + (lane >> 2);
        int k0 = kt * 16 + 2 * q;
        uint4 h4, l4; uint32_t hh, ll;
        split2(feats_s[r0*33 + k0],       feats_s[r0*33 + k0 + 1],       hh, ll); h4.x = hh; l4.x = ll;
        split2(feats_s[(r0+8)*33 + k0],   feats_s[(r0+8)*33 + k0 + 1],   hh, ll); h4.y = hh; l4.y = ll;
        split2(feats_s[r0*33 + k0 + 8],   feats_s[r0*33 + k0 + 9],       hh, ll); h4.z = hh; l4.z = ll;
        split2(feats_s[(r0+8)*33 + k0+8], feats_s[(r0+8)*33 + k0 + 9],   hh, ll); h4.w = hh; l4.w = ll;
        sAhi[(mtg * 16 + kt) * 32 + lane] = h4;
        sAlo[(mtg * 16 + kt) * 32 + lane] = l4;
    }

    // ---------------- layer loop (50 fine chunks, one kt each) ---------------
    // Single barrier per chunk: at iter g, issue chunk g+2 into slot (g+2)%3
    // (last read at iter g-1, protected by the top-of-iter barrier).
    float acc[2][8][4];
    #pragma unroll
    for (int m = 0; m < 2; ++m)
        #pragma unroll
        for (int t = 0; t < 8; ++t)
            #pragma unroll
            for (int j = 0; j < 4; ++j) acc[m][t][j] = 0.0f;

    const float* biasA[4] = {g_c1, b2, b3, b4};

    int g = 0;
    for (int L = 0; L < 4; ++L) {
        const int nc = (L == 0) ? 2 : 16;       // kt steps this layer
        const float* bias = biasA[L];
        for (int kt = 0; kt < nc; ++kt, ++g) {
            __syncthreads();          // ends iter g-1 (or: feats/A-frag build for g=0)
            if (g + 2 < NFINE) {
                const uint4* src = g_wimg + (size_t)(g + 2) * FINE_U4;
                uint32_t dst = sbase + BUF_OFF + ((g + 2) % 3) * BUFSZ;
                #pragma unroll
                for (int r = 0; r < 4; ++r) {
                    int idx = r * 256 + tid;
                    cpasync16(dst + idx * 16, src + idx);
                }
                CP_COMMIT();
            }
            // prefetch A-frags while the cp.async wait drains
            uint4 ah0 = sAhi[((mb * 2)     * 16 + kt) * 32 + lane];
            uint4 ah1 = sAhi[((mb * 2 + 1) * 16 + kt) * 32 + lane];
            uint4 al0 = sAlo[((mb * 2)     * 16 + kt) * 32 + lane];
            uint4 al1 = sAlo[((mb * 2 + 1) * 16 + kt) * 32 + lane];
            CP_WAIT2();               // chunk g resident
            const uint4* buf = bufs + (g % 3) * FINE_U4;
            const uint4* bp = buf + (nh * 8) * 32 + lane;
            #pragma unroll
            for (int t = 0; t < 8; ++t) {
                uint4 b = bp[t * 32];
                mma_bf16(acc[0][t], ah0, b.x, b.y);
                mma_bf16(acc[1][t], ah1, b.x, b.y);
                mma_bf16(acc[0][t], al0, b.x, b.y);
                mma_bf16(acc[1][t], al1, b.x, b.y);
                mma_bf16(acc[0][t], ah0, b.z, b.w);
                mma_bf16(acc[1][t], ah1, b.z, b.w);
            }

            if (kt == nc - 1) {
                // all warps' reads of this layer's A-frags must finish before
                // the epilogue overwrites them (closes the A-frag WAR race)
                __syncthreads();
                #pragma unroll
                for (int m = 0; m < 2; ++m) {
                    int mtg = mb * 2 + m;
                    #pragma unroll
                    for (int tt = 0; tt < 4; ++tt) {
                        float gv[2][4];
                        #pragma unroll
                        for (int u = 0; u < 2; ++u) {
                            int t = 2 * tt + u;
                            float b0  = __ldg(bias + nh * 64 + t * 8 + 2 * q);
                            float b1v = __ldg(bias + nh * 64 + t * 8 + 2 * q + 1);
                            gv[u][0] = gelu_exact(acc[m][t][0] + b0);
                            gv[u][1] = gelu_exact(acc[m][t][1] + b1v);
                            gv[u][2] = gelu_exact(acc[m][t][2] + b0);
                            gv[u][3] = gelu_exact(acc[m][t][3] + b1v);
                            acc[m][t][0] = 0.f; acc[m][t][1] = 0.f;
                            acc[m][t][2] = 0.f; acc[m][t][3] = 0.f;
                        }
                        uint4 h4, l4; uint32_t hh, ll;
                        split2(gv[0][0], gv[0][1], hh, ll); h4.x = hh; l4.x = ll;
                        split2(gv[0][2], gv[0][3], hh, ll); h4.y = hh; l4.y = ll;
                        split2(gv[1][0], gv[1][1], hh, ll); h4.z = hh; l4.z = ll;
                        split2(gv[1][2], gv[1][3], hh, ll); h4.w = hh; l4.w = ll;
                        int kt_out = nh * 4 + tt;
                        sAhi[(mtg * 16 + kt_out) * 32 + lane] = h4;
                        sAlo[(mtg * 16 + kt_out) * 32 + lane] = l4;
                    }
                }
            }
        }
    }

    // ---------------- layer 5: [64,256] @ [256,16]; warps with nh<2 ----------
    __syncthreads();              // L4 epilogue A-frags visible; slot reads done
    CP_WAIT0();                   // chunk 50 resident (slot 50%3 = 2)
    float* plain = (float*)(smem + BUF_OFF);                 // slot 0 reuse, [64][18]
    if (nh < 2) {
        const int nt = nh;
        const uint4* buf = bufs + (50 % 3) * FINE_U4;        // chunk 50 -> slot 2
        #pragma unroll
        for (int kt = 0; kt < 16; ++kt) {
            uint4 ah0 = sAhi[((mb * 2)     * 16 + kt) * 32 + lane];
            uint4 ah1 = sAhi[((mb * 2 + 1) * 16 + kt) * 32 + lane];
            uint4 al0 = sAlo[((mb * 2)     * 16 + kt) * 32 + lane];
            uint4 al1 = sAlo[((mb * 2 + 1) * 16 + kt) * 32 + lane];
            uint4 b = buf[kt * 64 + nt * 32 + lane];
            mma_bf16(acc[0][0], ah0, b.x, b.y);
            mma_bf16(acc[1][0], ah1, b.x, b.y);
            mma_bf16(acc[0][0], al0, b.x, b.y);
            mma_bf16(acc[1][0], al1, b.x, b.y);
            mma_bf16(acc[0][0], ah0, b.z, b.w);
            mma_bf16(acc[1][0], ah1, b.z, b.w);
        }
        #pragma unroll
        for (int m = 0; m < 2; ++m) {
            int r0 = (mb * 2 + m) * 16 + (lane >> 2);
            int c0 = nt * 8 + 2 * q;
            plain[r0 * 18 + c0]           = acc[m][0][0];
            plain[r0 * 18 + c0 + 1]       = acc[m][0][1];
            plain[(r0 + 8) * 18 + c0]     = acc[m][0][2];
            plain[(r0 + 8) * 18 + c0 + 1] = acc[m][0][3];
        }
    }
    __syncthreads();

    // ---------------- final epilogue -----------------------------------------
    if (tid < TILE_M) {
        int ig = blockRow + tid;
        if (ig < B) {
            float x[9];
            #pragma unroll
            for (int n = 0; n < 9; ++n) x[n] = plain[tid * 18 + n] + __ldg(b5 + n);
            float xs[9];
            xs[0]=x[0]; xs[4]=x[4]; xs[8]=x[8];
            xs[1]=xs[3]=0.5f*(x[1]+x[3]);
            xs[2]=xs[6]=0.5f*(x[2]+x[6]);
            xs[5]=xs[7]=0.5f*(x[5]+x[7]);
            float R[9], Ff[9], P[9];
            #pragma unroll
            for (int k = 0; k < 9; ++k) R[k]  = g_R[(size_t)ig * 9 + k];
            #pragma unroll
            for (int k = 0; k < 9; ++k) Ff[k] = Fg[(size_t)ig * 9 + k];
            #pragma unroll
            for (int rI = 0; rI < 3; ++rI)
                #pragma unroll
                for (int cI = 0; cI < 3; ++cI)
                    P[rI*3+cI] = R[rI*3+0]*xs[0*3+cI] + R[rI*3+1]*xs[1*3+cI] + R[rI*3+2]*xs[2*3+cI];
            #pragma unroll
            for (int rI = 0; rI < 3; ++rI)
                #pragma unroll
                for (int cI = 0; cI < 3; ++cI)
                    outg[(size_t)ig*9 + rI*3 + cI] =
                        P[rI*3+0]*Ff[cI*3+0] + P[rI*3+1]*Ff[cI*3+1] + P[rI*3+2]*Ff[cI*3+2];
        }
    }
}

// ---------------- launch ----------------
extern "C" void kernel_launch(void* const* d_in, const int* in_sizes, int n_in,
                              void* d_out, int out_size) {
    const float* F    = (const float*)d_in[0];
    const float* C    = (const float*)d_in[1];
    const float* emb  = (const float*)d_in[2];
    const int*   traj = (const int*)  d_in[3];
    const float* W1 = (const float*)d_in[4];
    const float* b1 = (const float*)d_in[5];
    const float* W2 = (const float*)d_in[6];
    const float* b2 = (const float*)d_in[7];
    const float* W3 = (const float*)d_in[8];
    const float* b3 = (const float*)d_in[9];
    const float* W4 = (const float*)d_in[10];
    const float* b4 = (const float*)d_in[11];
    const float* W5 = (const float*)d_in[12];
    const float* b5 = (const float*)d_in[13];
    float* out = (float*)d_out;

    int B = in_sizes[0] / 9;
    if (B > MAXB) B = MAXB;

    wprep_kernel<<<(26 * 2048 + 255) / 256, 256>>>(W1, W2, W3, W4, W5, emb, traj, b1);

    cudaFuncSetAttribute(mlp_mma_kernel, cudaFuncAttributeMaxDynamicSharedMemorySize, SMEM_TOTAL);
    int nblk = (B + TILE_M - 1) / TILE_M;
    mlp_mma_kernel<<<nblk, THREADS, SMEM_TOTAL>>>(F, C, b2, b3, b4, b5, out, B);
}

// round 9
// speedup vs baseline: 1.2570x; 1.0465x over previous
#include <cuda_runtime.h>
#include <cuda_bf16.h>
#include <math.h>
#include <stdint.h>

#define MAXB    262144
#define TILE_M  64
#define THREADS 256
#define EPSF    1e-6f

#define NFINE    51            // 16KB fine chunks, linear 0..50
#define FINE_U4  1024
#define BUFSZ    16384
#define SA_HI    0
#define SA_LO    32768
#define BUF_OFF  65536
#define SMEM_TOTAL (BUF_OFF + 3*BUFSZ)     // 114688 -> 2 CTAs/SM

// ---------------- device globals ----------------
__device__ __align__(128) uint4 g_wimg[26 * 2048];   // b-frag weight image
__device__ float g_c1[256];                          // b1 + latent @ W1[25:153]
__device__ float g_R[MAXB * 9];                      // polar rotations

// ---------------- helpers ----------------
__device__ __forceinline__ uint32_t smem_to_u32(const void* p) {
    uint32_t a;
    asm("{ .reg .u64 t; cvta.to.shared.u64 t, %1; cvt.u32.u64 %0, t; }" : "=r"(a) : "l"(p));
    return a;
}

__device__ __forceinline__ uint32_t packbf2(float lo, float hi) {
    uint32_t r;
    asm("cvt.rn.bf16x2.f32 %0, %1, %2;" : "=r"(r) : "f"(hi), "f"(lo));
    return r;
}

__device__ __forceinline__ void split2(float a, float b, uint32_t& h, uint32_t& l) {
    h = packbf2(a, b);
    float ha = __uint_as_float(h << 16);
    float hb = __uint_as_float(h & 0xffff0000u);
    l = packbf2(a - ha, b - hb);
}

__device__ __forceinline__ void mma_bf16(float* d, const uint4& a, uint32_t b0, uint32_t b1) {
    asm volatile("mma.sync.aligned.m16n8k16.row.col.f32.bf16.bf16.f32 "
        "{%0,%1,%2,%3}, {%4,%5,%6,%7}, {%8,%9}, {%0,%1,%2,%3};"
        : "+f"(d[0]), "+f"(d[1]), "+f"(d[2]), "+f"(d[3])
        : "r"(a.x), "r"(a.y), "r"(a.z), "r"(a.w), "r"(b0), "r"(b1));
}

__device__ __forceinline__ void cpasync16(uint32_t dst, const void* src) {
    asm volatile("cp.async.cg.shared.global [%0], [%1], 16;" :: "r"(dst), "l"(src));
}
#define CP_COMMIT() asm volatile("cp.async.commit_group;" ::: "memory")
#define CP_WAIT2()  asm volatile("cp.async.wait_group 2;" ::: "memory")
#define CP_WAIT0()  asm volatile("cp.async.wait_group 0;" ::: "memory")

__device__ __forceinline__ float gelu_exact(float x) {
    return 0.5f * x * (1.0f + erff(x * 0.70710678118654752f));
}

// ---------------- prep kernel: weight image + c1 fold (unchanged) ----------
__global__ void wprep_kernel(const float* __restrict__ W1, const float* __restrict__ W2,
                             const float* __restrict__ W3, const float* __restrict__ W4,
                             const float* __restrict__ W5,
                             const float* __restrict__ emb, const int* __restrict__ traj,
                             const float* __restrict__ b1) {
    if (blockIdx.x == 0) {
        int n = threadIdx.x;               // 256 threads
        const float* lat = emb + traj[0] * 128;
        float s = b1[n];
        #pragma unroll 4
        for (int d = 0; d < 128; ++d)
            s = fmaf(__ldg(lat + d), __ldg(W1 + (25 + d) * 256 + n), s);
        g_c1[n] = s;
    }

    int e = blockIdx.x * blockDim.x + threadIdx.x;
    if (e >= 26 * 2048) return;
    int gc = e >> 11, within = e & 2047;
    const float* W; int Kreal, Nreal, ld, kt, nt, lane;
    if (gc == 0) {
        W = W1; Kreal = 25; Nreal = 256; ld = 256;
        kt = within >> 10; int rem = within & 1023; nt = rem >> 5; lane = rem & 31;
    } else if (gc <= 8) {
        W = W2; Kreal = 256; Nreal = 256; ld = 256;
        kt = (gc - 1) * 2 + (within >> 10); int rem = within & 1023; nt = rem >> 5; lane = rem & 31;
    } else if (gc <= 16) {
        W = W3; Kreal = 256; Nreal = 256; ld = 256;
        kt = (gc - 9) * 2 + (within >> 10); int rem = within & 1023; nt = rem >> 5; lane = rem & 31;
    } else if (gc <= 24) {
        W = W4; Kreal = 256; Nreal = 256; ld = 256;
        kt = (gc - 17) * 2 + (within >> 10); int rem = within & 1023; nt = rem >> 5; lane = rem & 31;
    } else {
        if (within >= 1024) { g_wimg[e] = make_uint4(0u, 0u, 0u, 0u); return; }
        W = W5; Kreal = 256; Nreal = 9; ld = 9;
        kt = within >> 6; nt = (within >> 5) & 1; lane = within & 31;
    }
    int q = lane & 3, n = nt * 8 + (lane >> 2);
    int k0 = kt * 16 + 2 * q;
    float v00 = (k0     < Kreal && n < Nreal) ? W[(size_t)(k0    ) * ld + n] : 0.f;
    float v01 = (k0 + 1 < Kreal && n < Nreal) ? W[(size_t)(k0 + 1) * ld + n] : 0.f;
    float v10 = (k0 + 8 < Kreal && n < Nreal) ? W[(size_t)(k0 + 8) * ld + n] : 0.f;
    float v11 = (k0 + 9 < Kreal && n < Nreal) ? W[(size_t)(k0 + 9) * ld + n] : 0.f;
    uint4 o;
    uint32_t h, l;
    split2(v00, v01, h, l); o.x = h; o.z = l;
    split2(v10, v11, h, l); o.y = h; o.w = l;
    g_wimg[e] = o;
}

// ---------------- main kernel: warp-autonomous, barrier-free chunk loop -----
// Warp w owns cols n in [32w, 32w+32), ALL 64 rows. Each thread self-copies
// (cp.async) the exact 4 B uint4 words it later reads -> no block barriers
// inside layers; barriers only at layer boundaries (A-frag exchange).
__global__ void __launch_bounds__(THREADS, 2)
mlp_mma_kernel(const float* __restrict__ Fg, const float* __restrict__ Cg,
               const float* __restrict__ b2, const float* __restrict__ b3,
               const float* __restrict__ b4, const float* __restrict__ b5,
               float* __restrict__ outg, int B)
{
    extern __shared__ __align__(1024) char smem[];
    const uint32_t sbase = smem_to_u32(smem);
    const int tid  = threadIdx.x;
    const int lane = tid & 31;
    const int w    = tid >> 5;       // warp id 0..7: n-slice [32w, 32w+32)
    const int q    = lane & 3;
    const int blockRow = blockIdx.x * TILE_M;

    uint4* sAhi = (uint4*)(smem + SA_HI);
    uint4* sAlo = (uint4*)(smem + SA_LO);

    // per-thread self-copy addresses
    const uint32_t myDstBase = sbase + BUF_OFF + (uint32_t)w * 2048 + (uint32_t)lane * 16;
    const int mySrcBase = (w * 4) * 32 + lane;      // + j*32, + chunk*1024

    // issue chunks 0,1 (self-copy, warp-private regions)
    #pragma unroll
    for (int gg = 0; gg < 2; ++gg) {
        const uint4* src = g_wimg + gg * FINE_U4 + mySrcBase;
        uint32_t dst = myDstBase + gg * BUFSZ;
        #pragma unroll
        for (int j = 0; j < 4; ++j)
            cpasync16(dst + j * 512, src + j * 32);
        CP_COMMIT();
    }

    // ---------------- front-end (threads 0-63; feats -> slot-2 scratch) ------
    float* feats_s = (float*)(smem + BUF_OFF + 2 * BUFSZ);   // [64][33]
    if (tid < TILE_M) {
        int ig = blockRow + tid; if (ig >= B) ig = B - 1;
        float f[9], r[9];
        #pragma unroll
        for (int k = 0; k < 9; ++k) { f[k] = Fg[(size_t)ig * 9 + k]; r[k] = f[k]; }
        #pragma unroll
        for (int it = 0; it < 5; ++it) {
            float c00 = r[4]*r[8]-r[5]*r[7], c01 = r[5]*r[6]-r[3]*r[8], c02 = r[3]*r[7]-r[4]*r[6];
            float c10 = r[2]*r[7]-r[1]*r[8], c11 = r[0]*r[8]-r[2]*r[6], c12 = r[1]*r[6]-r[0]*r[7];
            float c20 = r[1]*r[5]-r[2]*r[4], c21 = r[2]*r[3]-r[0]*r[5], c22 = r[0]*r[4]-r[1]*r[3];
            float det = r[0]*c00 + r[1]*c01 + r[2]*c02;
            float ad  = fmaxf(fabsf(det), 1e-30f);
            float mu  = rcbrtf(ad);
            float s2  = 0.5f * mu;
            float s3  = 0.5f / (mu * det);
            float n0=s2*r[0]+s3*c00, n1=s2*r[1]+s3*c01, n2=s2*r[2]+s3*c02;
            float n3=s2*r[3]+s3*c10, n4=s2*r[4]+s3*c11, n5=s2*r[5]+s3*c12;
            float n6=s2*r[6]+s3*c20, n7=s2*r[7]+s3*c21, n8=s2*r[8]+s3*c22;
            r[0]=n0;r[1]=n1;r[2]=n2;r[3]=n3;r[4]=n4;r[5]=n5;r[6]=n6;r[7]=n7;r[8]=n8;
        }
        float a00=f[0]*f[0]+f[3]*f[3]+f[6]*f[6];
        float a01=f[0]*f[1]+f[3]*f[4]+f[6]*f[7];
        float a02=f[0]*f[2]+f[3]*f[5]+f[6]*f[8];
        float a11=f[1]*f[1]+f[4]*f[4]+f[7]*f[7];
        float a12=f[1]*f[2]+f[4]*f[5]+f[7]*f[8];
        float a22=f[2]*f[2]+f[5]*f[5]+f[8]*f[8];
        float qv = (a00+a11+a22)*(1.0f/3.0f);
        float d0 = a00-qv, d1 = a11-qv, d2 = a22-qv;
        float p2 = d0*d0+d1*d1+d2*d2+2.0f*(a01*a01+a02*a02+a12*a12);
        float e1,e2,e3;
        if (p2 < 1e-18f) { e1=e2=e3=qv; }
        else {
            float p = sqrtf(p2*(1.0f/6.0f)), invp = 1.0f/p;
            float b00=d0*invp,b11=d1*invp,b22=d2*invp;
            float b01=a01*invp,b02=a02*invp,b12=a12*invp;
            float detB = b00*(b11*b22-b12*b12)-b01*(b01*b22-b12*b02)+b02*(b01*b12-b11*b02);
            float rr = fminf(fmaxf(0.5f*detB,-1.0f),1.0f);
            float phi = acosf(rr)*(1.0f/3.0f);
            e1 = qv+2.0f*p*cosf(phi);
            e3 = qv+2.0f*p*cosf(phi+2.09439510239319549f);
            e2 = 3.0f*qv-e1-e3;
        }
        float detF = f[0]*(f[4]*f[8]-f[5]*f[7]) - f[1]*(f[3]*f[8]-f[5]*f[6]) + f[2]*(f[3]*f[7]-f[4]*f[6]);
        float f00c = fmaxf(f[0], EPSF);
        float ft[32];
        ft[0]=sqrtf(fmaxf(e1,0.f))-1.f; ft[1]=sqrtf(fmaxf(e2,0.f))-1.f; ft[2]=sqrtf(fmaxf(e3,0.f))-1.f;
        ft[3]=a00-1.f; ft[4]=a01; ft[5]=a02;
        ft[6]=a01; ft[7]=a11-1.f; ft[8]=a12;
        ft[9]=a02; ft[10]=a12; ft[11]=a22-1.f;
        ft[12]=detF-1.f; ft[13]=logf(detF)-1.f;
        ft[14]=f00c-1.f; ft[15]=logf(f00c)-1.f;
        #pragma unroll
        for (int j = 0; j < 9; ++j) ft[16+j] = Cg[(size_t)ig*9+j];
        #pragma unroll
        for (int j = 25; j < 32; ++j) ft[j] = 0.0f;
        #pragma unroll
        for (int k = 0; k < 32; ++k) feats_s[tid * 33 + k] = ft[k];
        #pragma unroll
        for (int k = 0; k < 9; ++k) g_R[(size_t)ig * 9 + k] = r[k];
    }
    __syncthreads();

    // build L1 A-frags: warp w -> (mtg = w>>1, kt = w&1)
    {
        int mtg = w >> 1;
        int kt  = w & 1;
        int r0 = mtg * 16 + (lane >> 2);
        int k0 = kt * 16 + 2 * q;
        uint4 h4, l4; uint32_t hh, ll;
        split2(feats_s[r0*33 + k0],       feats_s[r0*33 + k0 + 1],       hh, ll); h4.x = hh; l4.x = ll;
        split2(feats_s[(r0+8)*33 + k0],   feats_s[(r0+8)*33 + k0 + 1],   hh, ll); h4.y = hh; l4.y = ll;
        split2(feats_s[r0*33 + k0 + 8],   feats_s[r0*33 + k0 + 9],       hh, ll); h4.z = hh; l4.z = ll;
        split2(feats_s[(r0+8)*33 + k0+8], feats_s[(r0+8)*33 + k0 + 9],   hh, ll); h4.w = hh; l4.w = ll;
        sAhi[(mtg * 16 + kt) * 32 + lane] = h4;
        sAlo[(mtg * 16 + kt) * 32 + lane] = l4;
    }
    __syncthreads();   // feats reads + L1 A-frags complete before loop

    // ---------------- barrier-free layer loop --------------------------------
    float acc[4][4][4];
    #pragma unroll
    for (int m = 0; m < 4; ++m)
        #pragma unroll
        for (int t = 0; t < 4; ++t)
            #pragma unroll
            for (int j = 0; j < 4; ++j) acc[m][t][j] = 0.0f;

    const float* biasA[4] = {g_c1, b2, b3, b4};

    int g = 0;
    for (int L = 0; L < 4; ++L) {
        const int nc = (L == 0) ? 2 : 16;
        const float* bias = biasA[L];
        for (int kt = 0; kt < nc; ++kt, ++g) {
            // issue chunk g+2 into slot (g+2)%3 (own region only)
            if (g + 2 < NFINE) {
                const uint4* src = g_wimg + (g + 2) * FINE_U4 + mySrcBase;
                uint32_t dst = myDstBase + ((g + 2) % 3) * BUFSZ;
                #pragma unroll
                for (int j = 0; j < 4; ++j)
                    cpasync16(dst + j * 512, src + j * 32);
            }
            CP_COMMIT();
            // A-frags for this kt (all 4 row-groups)
            uint4 ah[4], al[4];
            #pragma unroll
            for (int m = 0; m < 4; ++m) {
                ah[m] = sAhi[(m * 16 + kt) * 32 + lane];
                al[m] = sAlo[(m * 16 + kt) * 32 + lane];
            }
            CP_WAIT2();               // own chunk-g copies resident
            const uint4* bp = (const uint4*)(smem + BUF_OFF + (g % 3) * BUFSZ + w * 2048) + lane;
            #pragma unroll
            for (int j = 0; j < 4; ++j) {
                uint4 b = bp[j * 32];
                #pragma unroll
                for (int m = 0; m < 4; ++m) {
                    mma_bf16(acc[m][j], ah[m], b.x, b.y);
                    mma_bf16(acc[m][j], al[m], b.x, b.y);
                    mma_bf16(acc[m][j], ah[m], b.z, b.w);
                }
            }
        }

        // -------- layer boundary: bias + GELU + split -> next A-frags --------
        __syncthreads();             // everyone done reading this layer's A-frags
        #pragma unroll
        for (int m = 0; m < 4; ++m) {
            #pragma unroll
            for (int tb = 0; tb < 2; ++tb) {
                float gv[2][4];
                #pragma unroll
                for (int u = 0; u < 2; ++u) {
                    int t = 2 * tb + u;
                    float b0  = __ldg(bias + w * 32 + t * 8 + 2 * q);
                    float b1v = __ldg(bias + w * 32 + t * 8 + 2 * q + 1);
                    gv[u][0] = gelu_exact(acc[m][t][0] + b0);
                    gv[u][1] = gelu_exact(acc[m][t][1] + b1v);
                    gv[u][2] = gelu_exact(acc[m][t][2] + b0);
                    gv[u][3] = gelu_exact(acc[m][t][3] + b1v);
                    acc[m][t][0] = 0.f; acc[m][t][1] = 0.f;
                    acc[m][t][2] = 0.f; acc[m][t][3] = 0.f;
                }
                uint4 h4, l4; uint32_t hh, ll;
                split2(gv[0][0], gv[0][1], hh, ll); h4.x = hh; l4.x = ll;
                split2(gv[0][2], gv[0][3], hh, ll); h4.y = hh; l4.y = ll;
                split2(gv[1][0], gv[1][1], hh, ll); h4.z = hh; l4.z = ll;
                split2(gv[1][2], gv[1][3], hh, ll); h4.w = hh; l4.w = ll;
                int kt_out = w * 2 + tb;
                sAhi[(m * 16 + kt_out) * 32 + lane] = h4;
                sAlo[(m * 16 + kt_out) * 32 + lane] = l4;
            }
        }
        __syncthreads();             // new A-frags visible
    }

    // ---------------- layer 5: all 8 warps, kt in {2w, 2w+1}, nt in {0,1} ----
    CP_WAIT0();                      // chunk 50 resident (slot 2, own region)
    {
        const uint4* bp = (const uint4*)(smem + BUF_OFF + 2 * BUFSZ + w * 2048) + lane;
        uint4 bw[4];
        #pragma unroll
        for (int j = 0; j < 4; ++j) bw[j] = bp[j * 32];   // j = 2u + nt -> kt=2w+u
        #pragma unroll
        for (int u = 0; u < 2; ++u) {
            int kt = 2 * w + u;
            #pragma unroll
            for (int m = 0; m < 4; ++m) {
                uint4 ah = sAhi[(m * 16 + kt) * 32 + lane];
                uint4 al = sAlo[(m * 16 + kt) * 32 + lane];
                #pragma unroll
                for (int nt = 0; nt < 2; ++nt) {
                    uint4 b = bw[2 * u + nt];
                    mma_bf16(acc[m][nt], ah, b.x, b.y);
                    mma_bf16(acc[m][nt], al, b.x, b.y);
                    mma_bf16(acc[m][nt], ah, b.z, b.w);
                }
            }
        }
        // write per-warp partial [64 rows x 16 cols] into slots 0/1 area
        float* part = (float*)(smem + BUF_OFF) + w * 1024;
        #pragma unroll
        for (int m = 0; m < 4; ++m)
            #pragma unroll
            for (int nt = 0; nt < 2; ++nt) {
                int r0 = m * 16 + (lane >> 2);
                int c0 = nt * 8 + 2 * q;
                part[r0 * 16 + c0]           = acc[m][nt][0];
                part[r0 * 16 + c0 + 1]       = acc[m][nt][1];
                part[(r0 + 8) * 16 + c0]     = acc[m][nt][2];
                part[(r0 + 8) * 16 + c0 + 1] = acc[m][nt][3];
            }
    }
    __syncthreads();

    // ---------------- final epilogue: reduce 8 partials, stress --------------
    if (tid < TILE_M) {
        int ig = blockRow + tid;
        if (ig < B) {
            const float* part = (const float*)(smem + BUF_OFF);
            float x[9];
            #pragma unroll
            for (int n = 0; n < 9; ++n) {
                float s = __ldg(b5 + n);
                #pragma unroll
                for (int ww = 0; ww < 8; ++ww)
                    s += part[ww * 1024 + tid * 16 + n];
                x[n] = s;
            }
            float xs[9];
            xs[0]=x[0]; xs[4]=x[4]; xs[8]=x[8];
            xs[1]=xs[3]=0.5f*(x[1]+x[3]);
            xs[2]=xs[6]=0.5f*(x[2]+x[6]);
            xs[5]=xs[7]=0.5f*(x[5]+x[7]);
            float R[9], Ff[9], P[9];
            #pragma unroll
            for (int k = 0; k < 9; ++k) R[k]  = g_R[(size_t)ig * 9 + k];
            #pragma unroll
            for (int k = 0; k < 9; ++k) Ff[k] = Fg[(size_t)ig * 9 + k];
            #pragma unroll
            for (int rI = 0; rI < 3; ++rI)
                #pragma unroll
                for (int cI = 0; cI < 3; ++cI)
                    P[rI*3+cI] = R[rI*3+0]*xs[0*3+cI] + R[rI*3+1]*xs[1*3+cI] + R[rI*3+2]*xs[2*3+cI];
            #pragma unroll
            for (int rI = 0; rI < 3; ++rI)
                #pragma unroll
                for (int cI = 0; cI < 3; ++cI)
                    outg[(size_t)ig*9 + rI*3 + cI] =
                        P[rI*3+0]*Ff[cI*3+0] + P[rI*3+1]*Ff[cI*3+1] + P[rI*3+2]*Ff[cI*3+2];
        }
    }
}

// ---------------- launch ----------------
extern "C" void kernel_launch(void* const* d_in, const int* in_sizes, int n_in,
                              void* d_out, int out_size) {
    const float* F    = (const float*)d_in[0];
    const float* C    = (const float*)d_in[1];
    const float* emb  = (const float*)d_in[2];
    const int*   traj = (const int*)  d_in[3];
    const float* W1 = (const float*)d_in[4];
    const float* b1 = (const float*)d_in[5];
    const float* W2 = (const float*)d_in[6];
    const float* b2 = (const float*)d_in[7];
    const float* W3 = (const float*)d_in[8];
    const float* b3 = (const float*)d_in[9];
    const float* W4 = (const float*)d_in[10];
    const float* b4 = (const float*)d_in[11];
    const float* W5 = (const float*)d_in[12];
    const float* b5 = (const float*)d_in[13];
    float* out = (float*)d_out;

    int B = in_sizes[0] / 9;
    if (B > MAXB) B = MAXB;

    wprep_kernel<<<(26 * 2048 + 255) / 256, 256>>>(W1, W2, W3, W4, W5, emb, traj, b1);

    cudaFuncSetAttribute(mlp_mma_kernel, cudaFuncAttributeMaxDynamicSharedMemorySize, SMEM_TOTAL);
    int nblk = (B + TILE_M - 1) / TILE_M;
    mlp_mma_kernel<<<nblk, THREADS, SMEM_TOTAL>>>(F, C, b2, b3, b4, b5, out, B);
}

// round 11
// speedup vs baseline: 1.3109x; 1.0429x over previous
#include <cuda_runtime.h>
#include <cuda_bf16.h>
#include <math.h>
#include <stdint.h>

#define MAXB    262144
#define TILE_M  64
#define THREADS 256
#define EPSF    1e-6f

#define NFINE    51            // 16KB fine chunks, linear 0..50
#define FINE_U4  1024
#define SA_HI    0
#define SA_LO    32768
#define SCRATCH  65536         // feats [64][33] early; L5 partials (32KB) late
#define SMEM_TOTAL (SCRATCH + 32768)       // 98304 -> 2 CTAs/SM

// ---------------- device globals ----------------
__device__ __align__(128) uint4 g_wimg[26 * 2048];   // b-frag weight image
__device__ float g_c1[256];                          // b1 + latent @ W1[25:153]
__device__ float g_R[MAXB * 9];                      // polar rotations

// ---------------- helpers ----------------
__device__ __forceinline__ uint32_t smem_to_u32(const void* p) {
    uint32_t a;
    asm("{ .reg .u64 t; cvta.to.shared.u64 t, %1; cvt.u32.u64 %0, t; }" : "=r"(a) : "l"(p));
    return a;
}

__device__ __forceinline__ uint32_t packbf2(float lo, float hi) {
    uint32_t r;
    asm("cvt.rn.bf16x2.f32 %0, %1, %2;" : "=r"(r) : "f"(hi), "f"(lo));
    return r;
}

__device__ __forceinline__ void split2(float a, float b, uint32_t& h, uint32_t& l) {
    h = packbf2(a, b);
    float ha = __uint_as_float(h << 16);
    float hb = __uint_as_float(h & 0xffff0000u);
    l = packbf2(a - ha, b - hb);
}

__device__ __forceinline__ void mma_bf16(float* d, const uint4& a, uint32_t b0, uint32_t b1) {
    asm volatile("mma.sync.aligned.m16n8k16.row.col.f32.bf16.bf16.f32 "
        "{%0,%1,%2,%3}, {%4,%5,%6,%7}, {%8,%9}, {%0,%1,%2,%3};"
        : "+f"(d[0]), "+f"(d[1]), "+f"(d[2]), "+f"(d[3])
        : "r"(a.x), "r"(a.y), "r"(a.z), "r"(a.w), "r"(b0), "r"(b1));
}

__device__ __forceinline__ float gelu_exact(float x) {
    return 0.5f * x * (1.0f + erff(x * 0.70710678118654752f));
}

// ---------------- prep kernel: weight image + c1 fold (unchanged) ----------
__global__ void wprep_kernel(const float* __restrict__ W1, const float* __restrict__ W2,
                             const float* __restrict__ W3, const float* __restrict__ W4,
                             const float* __restrict__ W5,
                             const float* __restrict__ emb, const int* __restrict__ traj,
                             const float* __restrict__ b1) {
    if (blockIdx.x == 0) {
        int n = threadIdx.x;               // 256 threads
        const float* lat = emb + traj[0] * 128;
        float s = b1[n];
        #pragma unroll 4
        for (int d = 0; d < 128; ++d)
            s = fmaf(__ldg(lat + d), __ldg(W1 + (25 + d) * 256 + n), s);
        g_c1[n] = s;
    }

    int e = blockIdx.x * blockDim.x + threadIdx.x;
    if (e >= 26 * 2048) return;
    int gc = e >> 11, within = e & 2047;
    const float* W; int Kreal, Nreal, ld, kt, nt, lane;
    if (gc == 0) {
        W = W1; Kreal = 25; Nreal = 256; ld = 256;
        kt = within >> 10; int rem = within & 1023; nt = rem >> 5; lane = rem & 31;
    } else if (gc <= 8) {
        W = W2; Kreal = 256; Nreal = 256; ld = 256;
        kt = (gc - 1) * 2 + (within >> 10); int rem = within & 1023; nt = rem >> 5; lane = rem & 31;
    } else if (gc <= 16) {
        W = W3; Kreal = 256; Nreal = 256; ld = 256;
        kt = (gc - 9) * 2 + (within >> 10); int rem = within & 1023; nt = rem >> 5; lane = rem & 31;
    } else if (gc <= 24) {
        W = W4; Kreal = 256; Nreal = 256; ld = 256;
        kt = (gc - 17) * 2 + (within >> 10); int rem = within & 1023; nt = rem >> 5; lane = rem & 31;
    } else {
        if (within >= 1024) { g_wimg[e] = make_uint4(0u, 0u, 0u, 0u); return; }
        W = W5; Kreal = 256; Nreal = 9; ld = 9;
        kt = within >> 6; nt = (within >> 5) & 1; lane = within & 31;
    }
    int q = lane & 3, n = nt * 8 + (lane >> 2);
    int k0 = kt * 16 + 2 * q;
    float v00 = (k0     < Kreal && n < Nreal) ? W[(size_t)(k0    ) * ld + n] : 0.f;
    float v01 = (k0 + 1 < Kreal && n < Nreal) ? W[(size_t)(k0 + 1) * ld + n] : 0.f;
    float v10 = (k0 + 8 < Kreal && n < Nreal) ? W[(size_t)(k0 + 8) * ld + n] : 0.f;
    float v11 = (k0 + 9 < Kreal && n < Nreal) ? W[(size_t)(k0 + 9) * ld + n] : 0.f;
    uint4 o;
    uint32_t h, l;
    split2(v00, v01, h, l); o.x = h; o.z = l;
    split2(v10, v11, h, l); o.y = h; o.w = l;
    g_wimg[e] = o;
}

// ---------------- main kernel: register-streamed B, no B smem at all --------
// Warp w owns cols [32w, 32w+32), all 64 rows. Each thread LDGs its own 4
// B uint4 words per chunk (L2-resident image) into a register double buffer.
// No cp.async, no ring, no per-chunk barriers; barriers only at layer bounds.
__global__ void __launch_bounds__(THREADS, 2)
mlp_mma_kernel(const float* __restrict__ Fg, const float* __restrict__ Cg,
               const float* __restrict__ b2, const float* __restrict__ b3,
               const float* __restrict__ b4, const float* __restrict__ b5,
               float* __restrict__ outg, int B)
{
    extern __shared__ __align__(1024) char smem[];
    const int tid  = threadIdx.x;
    const int lane = tid & 31;
    const int w    = tid >> 5;       // warp id 0..7: n-slice [32w, 32w+32)
    const int q    = lane & 3;
    const int blockRow = blockIdx.x * TILE_M;

    uint4* sAhi = (uint4*)(smem + SA_HI);
    uint4* sAlo = (uint4*)(smem + SA_LO);

    // this thread's B words: g_wimg[g*1024 + (w*4+j)*32 + lane]
    const uint4* mySrc = g_wimg + (w * 4) * 32 + lane;

    // preload chunk 0 into bc (covered by the front-end below)
    uint4 bc[4], bn[4];
    #pragma unroll
    for (int j = 0; j < 4; ++j) bc[j] = __ldg(mySrc + j * 32);

    // ---------------- front-end (threads 0-63; feats -> scratch) -------------
    float* feats_s = (float*)(smem + SCRATCH);   // [64][33]
    if (tid < TILE_M) {
        int ig = blockRow + tid; if (ig >= B) ig = B - 1;
        float f[9], r[9];
        #pragma unroll
        for (int k = 0; k < 9; ++k) { f[k] = Fg[(size_t)ig * 9 + k]; r[k] = f[k]; }
        #pragma unroll
        for (int it = 0; it < 5; ++it) {
            float c00 = r[4]*r[8]-r[5]*r[7], c01 = r[5]*r[6]-r[3]*r[8], c02 = r[3]*r[7]-r[4]*r[6];
            float c10 = r[2]*r[7]-r[1]*r[8], c11 = r[0]*r[8]-r[2]*r[6], c12 = r[1]*r[6]-r[0]*r[7];
            float c20 = r[1]*r[5]-r[2]*r[4], c21 = r[2]*r[3]-r[0]*r[5], c22 = r[0]*r[4]-r[1]*r[3];
            float det = r[0]*c00 + r[1]*c01 + r[2]*c02;
            float ad  = fmaxf(fabsf(det), 1e-30f);
            float mu  = rcbrtf(ad);
            float s2  = 0.5f * mu;
            float s3  = 0.5f / (mu * det);
            float n0=s2*r[0]+s3*c00, n1=s2*r[1]+s3*c01, n2=s2*r[2]+s3*c02;
            float n3=s2*r[3]+s3*c10, n4=s2*r[4]+s3*c11, n5=s2*r[5]+s3*c12;
            float n6=s2*r[6]+s3*c20, n7=s2*r[7]+s3*c21, n8=s2*r[8]+s3*c22;
            r[0]=n0;r[1]=n1;r[2]=n2;r[3]=n3;r[4]=n4;r[5]=n5;r[6]=n6;r[7]=n7;r[8]=n8;
        }
        float a00=f[0]*f[0]+f[3]*f[3]+f[6]*f[6];
        float a01=f[0]*f[1]+f[3]*f[4]+f[6]*f[7];
        float a02=f[0]*f[2]+f[3]*f[5]+f[6]*f[8];
        float a11=f[1]*f[1]+f[4]*f[4]+f[7]*f[7];
        float a12=f[1]*f[2]+f[4]*f[5]+f[7]*f[8];
        float a22=f[2]*f[2]+f[5]*f[5]+f[8]*f[8];
        float qv = (a00+a11+a22)*(1.0f/3.0f);
        float d0 = a00-qv, d1 = a11-qv, d2 = a22-qv;
        float p2 = d0*d0+d1*d1+d2*d2+2.0f*(a01*a01+a02*a02+a12*a12);
        float e1,e2,e3;
        if (p2 < 1e-18f) { e1=e2=e3=qv; }
        else {
            float p = sqrtf(p2*(1.0f/6.0f)), invp = 1.0f/p;
            float b00=d0*invp,b11=d1*invp,b22=d2*invp;
            float b01=a01*invp,b02=a02*invp,b12=a12*invp;
            float detB = b00*(b11*b22-b12*b12)-b01*(b01*b22-b12*b02)+b02*(b01*b12-b11*b02);
            float rr = fminf(fmaxf(0.5f*detB,-1.0f),1.0f);
            float phi = acosf(rr)*(1.0f/3.0f);
            e1 = qv+2.0f*p*cosf(phi);
            e3 = qv+2.0f*p*cosf(phi+2.09439510239319549f);
            e2 = 3.0f*qv-e1-e3;
        }
        float detF = f[0]*(f[4]*f[8]-f[5]*f[7]) - f[1]*(f[3]*f[8]-f[5]*f[6]) + f[2]*(f[3]*f[7]-f[4]*f[6]);
        float f00c = fmaxf(f[0], EPSF);
        float ft[32];
        ft[0]=sqrtf(fmaxf(e1,0.f))-1.f; ft[1]=sqrtf(fmaxf(e2,0.f))-1.f; ft[2]=sqrtf(fmaxf(e3,0.f))-1.f;
        ft[3]=a00-1.f; ft[4]=a01; ft[5]=a02;
        ft[6]=a01; ft[7]=a11-1.f; ft[8]=a12;
        ft[9]=a02; ft[10]=a12; ft[11]=a22-1.f;
        ft[12]=detF-1.f; ft[13]=logf(detF)-1.f;
        ft[14]=f00c-1.f; ft[15]=logf(f00c)-1.f;
        #pragma unroll
        for (int j = 0; j < 9; ++j) ft[16+j] = Cg[(size_t)ig*9+j];
        #pragma unroll
        for (int j = 25; j < 32; ++j) ft[j] = 0.0f;
        #pragma unroll
        for (int k = 0; k < 32; ++k) feats_s[tid * 33 + k] = ft[k];
        #pragma unroll
        for (int k = 0; k < 9; ++k) g_R[(size_t)ig * 9 + k] = r[k];
    }
    __syncthreads();

    // build L1 A-frags: warp w -> (mtg = w>>1, kt = w&1)
    {
        int mtg = w >> 1;
        int kt  = w & 1;
        int r0 = mtg * 16 + (lane >> 2);
        int k0 = kt * 16 + 2 * q;
        uint4 h4, l4; uint32_t hh, ll;
        split2(feats_s[r0*33 + k0],       feats_s[r0*33 + k0 + 1],       hh, ll); h4.x = hh; l4.x = ll;
        split2(feats_s[(r0+8)*33 + k0],   feats_s[(r0+8)*33 + k0 + 1],   hh, ll); h4.y = hh; l4.y = ll;
        split2(feats_s[r0*33 + k0 + 8],   feats_s[r0*33 + k0 + 9],       hh, ll); h4.z = hh; l4.z = ll;
        split2(feats_s[(r0+8)*33 + k0+8], feats_s[(r0+8)*33 + k0 + 9],   hh, ll); h4.w = hh; l4.w = ll;
        sAhi[(mtg * 16 + kt) * 32 + lane] = h4;
        sAlo[(mtg * 16 + kt) * 32 + lane] = l4;
    }
    __syncthreads();   // feats reads + L1 A-frags complete before loop

    // ---------------- layer loop: register-double-buffered B -----------------
    float acc[4][4][4];
    #pragma unroll
    for (int m = 0; m < 4; ++m)
        #pragma unroll
        for (int t = 0; t < 4; ++t)
            #pragma unroll
            for (int j = 0; j < 4; ++j) acc[m][t][j] = 0.0f;

    const float* biasA[4] = {g_c1, b2, b3, b4};

    int g = 0;
    for (int L = 0; L < 4; ++L) {
        const int nc = (L == 0) ? 2 : 16;
        const float* bias = biasA[L];
        for (int kt = 0; kt < nc; ++kt, ++g) {
            // prefetch next chunk's B words (pure LDG, one-epoch distance)
            if (g + 1 < NFINE) {
                const uint4* src = mySrc + (size_t)(g + 1) * FINE_U4;
                #pragma unroll
                for (int j = 0; j < 4; ++j) bn[j] = __ldg(src + j * 32);
            }
            // MMAs: m-outer (A transient), phase-major for dep spacing
            #pragma unroll
            for (int m = 0; m < 4; ++m) {
                uint4 ah = sAhi[(m * 16 + kt) * 32 + lane];
                uint4 al = sAlo[(m * 16 + kt) * 32 + lane];
                #pragma unroll
                for (int j = 0; j < 4; ++j) mma_bf16(acc[m][j], ah, bc[j].x, bc[j].y);
                #pragma unroll
                for (int j = 0; j < 4; ++j) mma_bf16(acc[m][j], al, bc[j].x, bc[j].y);
                #pragma unroll
                for (int j = 0; j < 4; ++j) mma_bf16(acc[m][j], ah, bc[j].z, bc[j].w);
            }
            #pragma unroll
            for (int j = 0; j < 4; ++j) bc[j] = bn[j];
        }

        // -------- layer boundary: bias + GELU + split -> next A-frags --------
        __syncthreads();             // everyone done reading this layer's A-frags
        #pragma unroll
        for (int m = 0; m < 4; ++m) {
            #pragma unroll
            for (int tb = 0; tb < 2; ++tb) {
                float gv[2][4];
                #pragma unroll
                for (int u = 0; u < 2; ++u) {
                    int t = 2 * tb + u;
                    float b0  = __ldg(bias + w * 32 + t * 8 + 2 * q);
                    float b1v = __ldg(bias + w * 32 + t * 8 + 2 * q + 1);
                    gv[u][0] = gelu_exact(acc[m][t][0] + b0);
                    gv[u][1] = gelu_exact(acc[m][t][1] + b1v);
                    gv[u][2] = gelu_exact(acc[m][t][2] + b0);
                    gv[u][3] = gelu_exact(acc[m][t][3] + b1v);
                    acc[m][t][0] = 0.f; acc[m][t][1] = 0.f;
                    acc[m][t][2] = 0.f; acc[m][t][3] = 0.f;
                }
                uint4 h4, l4; uint32_t hh, ll;
                split2(gv[0][0], gv[0][1], hh, ll); h4.x = hh; l4.x = ll;
                split2(gv[0][2], gv[0][3], hh, ll); h4.y = hh; l4.y = ll;
                split2(gv[1][0], gv[1][1], hh, ll); h4.z = hh; l4.z = ll;
                split2(gv[1][2], gv[1][3], hh, ll); h4.w = hh; l4.w = ll;
                int kt_out = w * 2 + tb;
                sAhi[(m * 16 + kt_out) * 32 + lane] = h4;
                sAlo[(m * 16 + kt_out) * 32 + lane] = l4;
            }
        }
        __syncthreads();             // new A-frags visible
    }

    // ---------------- layer 5: bc already holds chunk 50 ---------------------
    // kt in {2w, 2w+1} via j = 2u + nt
    {
        #pragma unroll
        for (int u = 0; u < 2; ++u) {
            int kt = 2 * w + u;
            #pragma unroll
            for (int m = 0; m < 4; ++m) {
                uint4 ah = sAhi[(m * 16 + kt) * 32 + lane];
                uint4 al = sAlo[(m * 16 + kt) * 32 + lane];
                #pragma unroll
                for (int nt = 0; nt < 2; ++nt) {
                    uint4 b = bc[2 * u + nt];
                    mma_bf16(acc[m][nt], ah, b.x, b.y);
                    mma_bf16(acc[m][nt], al, b.x, b.y);
                    mma_bf16(acc[m][nt], ah, b.z, b.w);
                }
            }
        }
        // write per-warp partial [64 rows x 16 cols] into scratch
        float* part = (float*)(smem + SCRATCH) + w * 1024;
        #pragma unroll
        for (int m = 0; m < 4; ++m)
            #pragma unroll
            for (int nt = 0; nt < 2; ++nt) {
                int r0 = m * 16 + (lane >> 2);
                int c0 = nt * 8 + 2 * q;
                part[r0 * 16 + c0]           = acc[m][nt][0];
                part[r0 * 16 + c0 + 1]       = acc[m][nt][1];
                part[(r0 + 8) * 16 + c0]     = acc[m][nt][2];
                part[(r0 + 8) * 16 + c0 + 1] = acc[m][nt][3];
            }
    }
    __syncthreads();

    // ---------------- final epilogue: reduce 8 partials, stress --------------
    if (tid < TILE_M) {
        int ig = blockRow + tid;
        if (ig < B) {
            const float* part = (const float*)(smem + SCRATCH);
            float x[9];
            #pragma unroll
            for (int n = 0; n < 9; ++n) {
                float s = __ldg(b5 + n);
                #pragma unroll
                for (int ww = 0; ww < 8; ++ww)
                    s += part[ww * 1024 + tid * 16 + n];
                x[n] = s;
            }
            float xs[9];
            xs[0]=x[0]; xs[4]=x[4]; xs[8]=x[8];
            xs[1]=xs[3]=0.5f*(x[1]+x[3]);
            xs[2]=xs[6]=0.5f*(x[2]+x[6]);
            xs[5]=xs[7]=0.5f*(x[5]+x[7]);
            float R[9], Ff[9], P[9];
            #pragma unroll
            for (int k = 0; k < 9; ++k) R[k]  = g_R[(size_t)ig * 9 + k];
            #pragma unroll
            for (int k = 0; k < 9; ++k) Ff[k] = Fg[(size_t)ig * 9 + k];
            #pragma unroll
            for (int rI = 0; rI < 3; ++rI)
                #pragma unroll
                for (int cI = 0; cI < 3; ++cI)
                    P[rI*3+cI] = R[rI*3+0]*xs[0*3+cI] + R[rI*3+1]*xs[1*3+cI] + R[rI*3+2]*xs[2*3+cI];
            #pragma unroll
            for (int rI = 0; rI < 3; ++rI)
                #pragma unroll
                for (int cI = 0; cI < 3; ++cI)
                    outg[(size_t)ig*9 + rI*3 + cI] =
                        P[rI*3+0]*Ff[cI*3+0] + P[rI*3+1]*Ff[cI*3+1] + P[rI*3+2]*Ff[cI*3+2];
        }
    }
}

// ---------------- launch ----------------
extern "C" void kernel_launch(void* const* d_in, const int* in_sizes, int n_in,
                              void* d_out, int out_size) {
    const float* F    = (const float*)d_in[0];
    const float* C    = (const float*)d_in[1];
    const float* emb  = (const float*)d_in[2];
    const int*   traj = (const int*)  d_in[3];
    const float* W1 = (const float*)d_in[4];
    const float* b1 = (const float*)d_in[5];
    const float* W2 = (const float*)d_in[6];
    const float* b2 = (const float*)d_in[7];
    const float* W3 = (const float*)d_in[8];
    const float* b3 = (const float*)d_in[9];
    const float* W4 = (const float*)d_in[10];
    const float* b4 = (const float*)d_in[11];
    const float* W5 = (const float*)d_in[12];
    const float* b5 = (const float*)d_in[13];
    float* out = (float*)d_out;

    int B = in_sizes[0] / 9;
    if (B > MAXB) B = MAXB;

    wprep_kernel<<<(26 * 2048 + 255) / 256, 256>>>(W1, W2, W3, W4, W5, emb, traj, b1);

    cudaFuncSetAttribute(mlp_mma_kernel, cudaFuncAttributeMaxDynamicSharedMemorySize, SMEM_TOTAL);
    int nblk = (B + TILE_M - 1) / TILE_M;
    mlp_mma_kernel<<<nblk, THREADS, SMEM_TOTAL>>>(F, C, b2, b3, b4, b5, out, B);
}

// round 12
// speedup vs baseline: 1.3431x; 1.0246x over previous
#include <cuda_runtime.h>
#include <cuda_bf16.h>
#include <math.h>
#include <stdint.h>

#define MAXB    262144
#define TILE_M  64
#define THREADS 256
#define EPSF    1e-6f

#define NFINE    51            // 16KB fine chunks, linear 0..50
#define FINE_U4  1024
#define SA_HI    0
#define SA_LO    32768
#define SCRATCH  65536         // feats [64][33] early; L5 partials (32KB) late
#define SMEM_TOTAL (SCRATCH + 32768)       // 98304 -> 2 CTAs/SM

// ---------------- device globals ----------------
__device__ __align__(128) uint4 g_wimg[26 * 2048];   // b-frag weight image
__device__ float g_c1[256];                          // b1 + latent @ W1[25:153]
__device__ float g_R[MAXB * 9];                      // polar rotations

// ---------------- helpers ----------------
__device__ __forceinline__ uint32_t packbf2(float lo, float hi) {
    uint32_t r;
    asm("cvt.rn.bf16x2.f32 %0, %1, %2;" : "=r"(r) : "f"(hi), "f"(lo));
    return r;
}

__device__ __forceinline__ void split2(float a, float b, uint32_t& h, uint32_t& l) {
    h = packbf2(a, b);
    float ha = __uint_as_float(h << 16);
    float hb = __uint_as_float(h & 0xffff0000u);
    l = packbf2(a - ha, b - hb);
}

__device__ __forceinline__ void mma_bf16(float* d, const uint4& a, uint32_t b0, uint32_t b1) {
    asm volatile("mma.sync.aligned.m16n8k16.row.col.f32.bf16.bf16.f32 "
        "{%0,%1,%2,%3}, {%4,%5,%6,%7}, {%8,%9}, {%0,%1,%2,%3};"
        : "+f"(d[0]), "+f"(d[1]), "+f"(d[2]), "+f"(d[3])
        : "r"(a.x), "r"(a.y), "r"(a.z), "r"(a.w), "r"(b0), "r"(b1));
}

__device__ __forceinline__ float gelu_exact(float x) {
    return 0.5f * x * (1.0f + erff(x * 0.70710678118654752f));
}

// ---------------- prep kernel: weight image + c1 fold (unchanged) ----------
__global__ void wprep_kernel(const float* __restrict__ W1, const float* __restrict__ W2,
                             const float* __restrict__ W3, const float* __restrict__ W4,
                             const float* __restrict__ W5,
                             const float* __restrict__ emb, const int* __restrict__ traj,
                             const float* __restrict__ b1) {
    if (blockIdx.x == 0) {
        int n = threadIdx.x;               // 256 threads
        const float* lat = emb + traj[0] * 128;
        float s = b1[n];
        #pragma unroll 4
        for (int d = 0; d < 128; ++d)
            s = fmaf(__ldg(lat + d), __ldg(W1 + (25 + d) * 256 + n), s);
        g_c1[n] = s;
    }

    int e = blockIdx.x * blockDim.x + threadIdx.x;
    if (e >= 26 * 2048) return;
    int gc = e >> 11, within = e & 2047;
    const float* W; int Kreal, Nreal, ld, kt, nt, lane;
    if (gc == 0) {
        W = W1; Kreal = 25; Nreal = 256; ld = 256;
        kt = within >> 10; int rem = within & 1023; nt = rem >> 5; lane = rem & 31;
    } else if (gc <= 8) {
        W = W2; Kreal = 256; Nreal = 256; ld = 256;
        kt = (gc - 1) * 2 + (within >> 10); int rem = within & 1023; nt = rem >> 5; lane = rem & 31;
    } else if (gc <= 16) {
        W = W3; Kreal = 256; Nreal = 256; ld = 256;
        kt = (gc - 9) * 2 + (within >> 10); int rem = within & 1023; nt = rem >> 5; lane = rem & 31;
    } else if (gc <= 24) {
        W = W4; Kreal = 256; Nreal = 256; ld = 256;
        kt = (gc - 17) * 2 + (within >> 10); int rem = within & 1023; nt = rem >> 5; lane = rem & 31;
    } else {
        if (within >= 1024) { g_wimg[e] = make_uint4(0u, 0u, 0u, 0u); return; }
        W = W5; Kreal = 256; Nreal = 9; ld = 9;
        kt = within >> 6; nt = (within >> 5) & 1; lane = within & 31;
    }
    int q = lane & 3, n = nt * 8 + (lane >> 2);
    int k0 = kt * 16 + 2 * q;
    float v00 = (k0     < Kreal && n < Nreal) ? W[(size_t)(k0    ) * ld + n] : 0.f;
    float v01 = (k0 + 1 < Kreal && n < Nreal) ? W[(size_t)(k0 + 1) * ld + n] : 0.f;
    float v10 = (k0 + 8 < Kreal && n < Nreal) ? W[(size_t)(k0 + 8) * ld + n] : 0.f;
    float v11 = (k0 + 9 < Kreal && n < Nreal) ? W[(size_t)(k0 + 9) * ld + n] : 0.f;
    uint4 o;
    uint32_t h, l;
    split2(v00, v01, h, l); o.x = h; o.z = l;
    split2(v10, v11, h, l); o.y = h; o.w = l;
    g_wimg[e] = o;
}

// ---------------- main kernel: register-streamed B, 2x-unrolled epochs ------
__global__ void __launch_bounds__(THREADS, 2)
mlp_mma_kernel(const float* __restrict__ Fg, const float* __restrict__ Cg,
               const float* __restrict__ b2, const float* __restrict__ b3,
               const float* __restrict__ b4, const float* __restrict__ b5,
               float* __restrict__ outg, int B)
{
    extern __shared__ __align__(1024) char smem[];
    const int tid  = threadIdx.x;
    const int lane = tid & 31;
    const int w    = tid >> 5;       // warp id 0..7: n-slice [32w, 32w+32)
    const int q    = lane & 3;
    const int blockRow = blockIdx.x * TILE_M;

    uint4* sAhi = (uint4*)(smem + SA_HI);
    uint4* sAlo = (uint4*)(smem + SA_LO);

    // this thread's B words: g_wimg[g*1024 + (w*4+j)*32 + lane]
    const uint4* srcPtr = g_wimg + (w * 4) * 32 + lane;

    // preload chunk 0 into bc (covered by the front-end below)
    uint4 bc[4], bn[4];
    #pragma unroll
    for (int j = 0; j < 4; ++j) bc[j] = __ldg(srcPtr + j * 32);
    srcPtr += FINE_U4;      // now points at chunk 1

    // ---------------- front-end (threads 0-63; feats -> scratch) -------------
    float* feats_s = (float*)(smem + SCRATCH);   // [64][33]
    if (tid < TILE_M) {
        int ig = blockRow + tid; if (ig >= B) ig = B - 1;
        float f[9], r[9];
        #pragma unroll
        for (int k = 0; k < 9; ++k) { f[k] = Fg[(size_t)ig * 9 + k]; r[k] = f[k]; }
        #pragma unroll
        for (int it = 0; it < 5; ++it) {
            float c00 = r[4]*r[8]-r[5]*r[7], c01 = r[5]*r[6]-r[3]*r[8], c02 = r[3]*r[7]-r[4]*r[6];
            float c10 = r[2]*r[7]-r[1]*r[8], c11 = r[0]*r[8]-r[2]*r[6], c12 = r[1]*r[6]-r[0]*r[7];
            float c20 = r[1]*r[5]-r[2]*r[4], c21 = r[2]*r[3]-r[0]*r[5], c22 = r[0]*r[4]-r[1]*r[3];
            float det = r[0]*c00 + r[1]*c01 + r[2]*c02;
            float ad  = fmaxf(fabsf(det), 1e-30f);
            float mu  = rcbrtf(ad);
            float s2  = 0.5f * mu;
            float s3  = 0.5f / (mu * det);
            float n0=s2*r[0]+s3*c00, n1=s2*r[1]+s3*c01, n2=s2*r[2]+s3*c02;
            float n3=s2*r[3]+s3*c10, n4=s2*r[4]+s3*c11, n5=s2*r[5]+s3*c12;
            float n6=s2*r[6]+s3*c20, n7=s2*r[7]+s3*c21, n8=s2*r[8]+s3*c22;
            r[0]=n0;r[1]=n1;r[2]=n2;r[3]=n3;r[4]=n4;r[5]=n5;r[6]=n6;r[7]=n7;r[8]=n8;
        }
        float a00=f[0]*f[0]+f[3]*f[3]+f[6]*f[6];
        float a01=f[0]*f[1]+f[3]*f[4]+f[6]*f[7];
        float a02=f[0]*f[2]+f[3]*f[5]+f[6]*f[8];
        float a11=f[1]*f[1]+f[4]*f[4]+f[7]*f[7];
        float a12=f[1]*f[2]+f[4]*f[5]+f[7]*f[8];
        float a22=f[2]*f[2]+f[5]*f[5]+f[8]*f[8];
        float qv = (a00+a11+a22)*(1.0f/3.0f);
        float d0 = a00-qv, d1 = a11-qv, d2 = a22-qv;
        float p2 = d0*d0+d1*d1+d2*d2+2.0f*(a01*a01+a02*a02+a12*a12);
        float e1,e2,e3;
        if (p2 < 1e-18f) { e1=e2=e3=qv; }
        else {
            float p = sqrtf(p2*(1.0f/6.0f)), invp = 1.0f/p;
            float b00=d0*invp,b11=d1*invp,b22=d2*invp;
            float b01=a01*invp,b02=a02*invp,b12=a12*invp;
            float detB = b00*(b11*b22-b12*b12)-b01*(b01*b22-b12*b02)+b02*(b01*b12-b11*b02);
            float rr = fminf(fmaxf(0.5f*detB,-1.0f),1.0f);
            float phi = acosf(rr)*(1.0f/3.0f);
            e1 = qv+2.0f*p*cosf(phi);
            e3 = qv+2.0f*p*cosf(phi+2.09439510239319549f);
            e2 = 3.0f*qv-e1-e3;
        }
        float detF = f[0]*(f[4]*f[8]-f[5]*f[7]) - f[1]*(f[3]*f[8]-f[5]*f[6]) + f[2]*(f[3]*f[7]-f[4]*f[6]);
        float f00c = fmaxf(f[0], EPSF);
        float ft[32];
        ft[0]=sqrtf(fmaxf(e1,0.f))-1.f; ft[1]=sqrtf(fmaxf(e2,0.f))-1.f; ft[2]=sqrtf(fmaxf(e3,0.f))-1.f;
        ft[3]=a00-1.f; ft[4]=a01; ft[5]=a02;
        ft[6]=a01; ft[7]=a11-1.f; ft[8]=a12;
        ft[9]=a02; ft[10]=a12; ft[11]=a22-1.f;
        ft[12]=detF-1.f; ft[13]=logf(detF)-1.f;
        ft[14]=f00c-1.f; ft[15]=logf(f00c)-1.f;
        #pragma unroll
        for (int j = 0; j < 9; ++j) ft[16+j] = Cg[(size_t)ig*9+j];
        #pragma unroll
        for (int j = 25; j < 32; ++j) ft[j] = 0.0f;
        #pragma unroll
        for (int k = 0; k < 32; ++k) feats_s[tid * 33 + k] = ft[k];
        #pragma unroll
        for (int k = 0; k < 9; ++k) g_R[(size_t)ig * 9 + k] = r[k];
    }
    __syncthreads();

    // build L1 A-frags: warp w -> (mtg = w>>1, kt = w&1)
    {
        int mtg = w >> 1;
        int kt  = w & 1;
        int r0 = mtg * 16 + (lane >> 2);
        int k0 = kt * 16 + 2 * q;
        uint4 h4, l4; uint32_t hh, ll;
        split2(feats_s[r0*33 + k0],       feats_s[r0*33 + k0 + 1],       hh, ll); h4.x = hh; l4.x = ll;
        split2(feats_s[(r0+8)*33 + k0],   feats_s[(r0+8)*33 + k0 + 1],   hh, ll); h4.y = hh; l4.y = ll;
        split2(feats_s[r0*33 + k0 + 8],   feats_s[r0*33 + k0 + 9],       hh, ll); h4.z = hh; l4.z = ll;
        split2(feats_s[(r0+8)*33 + k0+8], feats_s[(r0+8)*33 + k0 + 9],   hh, ll); h4.w = hh; l4.w = ll;
        sAhi[(mtg * 16 + kt) * 32 + lane] = h4;
        sAlo[(mtg * 16 + kt) * 32 + lane] = l4;
    }
    __syncthreads();   // feats reads + L1 A-frags complete before loop

    // ---------------- layer loop: 2x-unrolled, alternating B buffers ---------
    float acc[4][4][4];
    #pragma unroll
    for (int m = 0; m < 4; ++m)
        #pragma unroll
        for (int t = 0; t < 4; ++t)
            #pragma unroll
            for (int j = 0; j < 4; ++j) acc[m][t][j] = 0.0f;

    const float* biasA[4] = {g_c1, b2, b3, b4};

    for (int L = 0; L < 4; ++L) {
        const int nc = (L == 0) ? 2 : 16;       // even for all layers
        const float* bias = biasA[L];
        for (int kt = 0; kt < nc; kt += 2) {
            // ---- even epoch: consume bc, prefetch next chunk into bn --------
            #pragma unroll
            for (int j = 0; j < 4; ++j) bn[j] = __ldg(srcPtr + j * 32);
            srcPtr += FINE_U4;
            #pragma unroll
            for (int m = 0; m < 4; ++m) {
                uint4 ah = sAhi[(m * 16 + kt) * 32 + lane];
                uint4 al = sAlo[(m * 16 + kt) * 32 + lane];
                #pragma unroll
                for (int j = 0; j < 4; ++j) mma_bf16(acc[m][j], ah, bc[j].x, bc[j].y);
                #pragma unroll
                for (int j = 0; j < 4; ++j) mma_bf16(acc[m][j], al, bc[j].x, bc[j].y);
                #pragma unroll
                for (int j = 0; j < 4; ++j) mma_bf16(acc[m][j], ah, bc[j].z, bc[j].w);
            }
            // ---- odd epoch: consume bn, prefetch next chunk into bc ---------
            // (final odd epoch of L4 prefetches chunk 50 = L5 weights into bc)
            #pragma unroll
            for (int j = 0; j < 4; ++j) bc[j] = __ldg(srcPtr + j * 32);
            srcPtr += FINE_U4;
            #pragma unroll
            for (int m = 0; m < 4; ++m) {
                uint4 ah = sAhi[(m * 16 + kt + 1) * 32 + lane];
                uint4 al = sAlo[(m * 16 + kt + 1) * 32 + lane];
                #pragma unroll
                for (int j = 0; j < 4; ++j) mma_bf16(acc[m][j], ah, bn[j].x, bn[j].y);
                #pragma unroll
                for (int j = 0; j < 4; ++j) mma_bf16(acc[m][j], al, bn[j].x, bn[j].y);
                #pragma unroll
                for (int j = 0; j < 4; ++j) mma_bf16(acc[m][j], ah, bn[j].z, bn[j].w);
            }
        }

        // -------- layer boundary: bias + GELU + split -> next A-frags --------
        __syncthreads();             // everyone done reading this layer's A-frags
        float bb0[2][2], bb1[2][2];  // hoisted bias: [tb][u]
        #pragma unroll
        for (int tb = 0; tb < 2; ++tb)
            #pragma unroll
            for (int u = 0; u < 2; ++u) {
                int t = 2 * tb + u;
                bb0[tb][u] = __ldg(bias + w * 32 + t * 8 + 2 * q);
                bb1[tb][u] = __ldg(bias + w * 32 + t * 8 + 2 * q + 1);
            }
        #pragma unroll
        for (int m = 0; m < 4; ++m) {
            #pragma unroll
            for (int tb = 0; tb < 2; ++tb) {
                float gv[2][4];
                #pragma unroll
                for (int u = 0; u < 2; ++u) {
                    int t = 2 * tb + u;
                    gv[u][0] = gelu_exact(acc[m][t][0] + bb0[tb][u]);
                    gv[u][1] = gelu_exact(acc[m][t][1] + bb1[tb][u]);
                    gv[u][2] = gelu_exact(acc[m][t][2] + bb0[tb][u]);
                    gv[u][3] = gelu_exact(acc[m][t][3] + bb1[tb][u]);
                    acc[m][t][0] = 0.f; acc[m][t][1] = 0.f;
                    acc[m][t][2] = 0.f; acc[m][t][3] = 0.f;
                }
                uint4 h4, l4; uint32_t hh, ll;
                split2(gv[0][0], gv[0][1], hh, ll); h4.x = hh; l4.x = ll;
                split2(gv[0][2], gv[0][3], hh, ll); h4.y = hh; l4.y = ll;
                split2(gv[1][0], gv[1][1], hh, ll); h4.z = hh; l4.z = ll;
                split2(gv[1][2], gv[1][3], hh, ll); h4.w = hh; l4.w = ll;
                int kt_out = w * 2 + tb;
                sAhi[(m * 16 + kt_out) * 32 + lane] = h4;
                sAlo[(m * 16 + kt_out) * 32 + lane] = l4;
            }
        }
        __syncthreads();             // new A-frags visible
    }

    // ---------------- layer 5: bc holds chunk 50 -----------------------------
    // kt in {2w, 2w+1} via j = 2u + nt
    {
        #pragma unroll
        for (int u = 0; u < 2; ++u) {
            int kt = 2 * w + u;
            #pragma unroll
            for (int m = 0; m < 4; ++m) {
                uint4 ah = sAhi[(m * 16 + kt) * 32 + lane];
                uint4 al = sAlo[(m * 16 + kt) * 32 + lane];
                #pragma unroll
                for (int nt = 0; nt < 2; ++nt) {
                    uint4 b = bc[2 * u + nt];
                    mma_bf16(acc[m][nt], ah, b.x, b.y);
                    mma_bf16(acc[m][nt], al, b.x, b.y);
                    mma_bf16(acc[m][nt], ah, b.z, b.w);
                }
            }
        }
        // write per-warp partial [64 rows x 16 cols] into scratch
        float* part = (float*)(smem + SCRATCH) + w * 1024;
        #pragma unroll
        for (int m = 0; m < 4; ++m)
            #pragma unroll
            for (int nt = 0; nt < 2; ++nt) {
                int r0 = m * 16 + (lane >> 2);
                int c0 = nt * 8 + 2 * q;
                part[r0 * 16 + c0]           = acc[m][nt][0];
                part[r0 * 16 + c0 + 1]       = acc[m][nt][1];
                part[(r0 + 8) * 16 + c0]     = acc[m][nt][2];
                part[(r0 + 8) * 16 + c0 + 1] = acc[m][nt][3];
            }
    }
    __syncthreads();

    // ---------------- final epilogue: reduce 8 partials, stress --------------
    if (tid < TILE_M) {
        int ig = blockRow + tid;
        if (ig < B) {
            const float* part = (const float*)(smem + SCRATCH);
            float x[9];
            #pragma unroll
            for (int n = 0; n < 9; ++n) {
                float s = __ldg(b5 + n);
                #pragma unroll
                for (int ww = 0; ww < 8; ++ww)
                    s += part[ww * 1024 + tid * 16 + n];
                x[n] = s;
            }
            float xs[9];
            xs[0]=x[0]; xs[4]=x[4]; xs[8]=x[8];
            xs[1]=xs[3]=0.5f*(x[1]+x[3]);
            xs[2]=xs[6]=0.5f*(x[2]+x[6]);
            xs[5]=xs[7]=0.5f*(x[5]+x[7]);
            float R[9], Ff[9], P[9];
            #pragma unroll
            for (int k = 0; k < 9; ++k) R[k]  = g_R[(size_t)ig * 9 + k];
            #pragma unroll
            for (int k = 0; k < 9; ++k) Ff[k] = Fg[(size_t)ig * 9 + k];
            #pragma unroll
            for (int rI = 0; rI < 3; ++rI)
                #pragma unroll
                for (int cI = 0; cI < 3; ++cI)
                    P[rI*3+cI] = R[rI*3+0]*xs[0*3+cI] + R[rI*3+1]*xs[1*3+cI] + R[rI*3+2]*xs[2*3+cI];
            #pragma unroll
            for (int rI = 0; rI < 3; ++rI)
                #pragma unroll
                for (int cI = 0; cI < 3; ++cI)
                    outg[(size_t)ig*9 + rI*3 + cI] =
                        P[rI*3+0]*Ff[cI*3+0] + P[rI*3+1]*Ff[cI*3+1] + P[rI*3+2]*Ff[cI*3+2];
        }
    }
}

// ---------------- launch ----------------
extern "C" void kernel_launch(void* const* d_in, const int* in_sizes, int n_in,
                              void* d_out, int out_size) {
    const float* F    = (const float*)d_in[0];
    const float* C    = (const float*)d_in[1];
    const float* emb  = (const float*)d_in[2];
    const int*   traj = (const int*)  d_in[3];
    const float* W1 = (const float*)d_in[4];
    const float* b1 = (const float*)d_in[5];
    const float* W2 = (const float*)d_in[6];
    const float* b2 = (const float*)d_in[7];
    const float* W3 = (const float*)d_in[8];
    const float* b3 = (const float*)d_in[9];
    const float* W4 = (const float*)d_in[10];
    const float* b4 = (const float*)d_in[11];
    const float* W5 = (const float*)d_in[12];
    const float* b5 = (const float*)d_in[13];
    float* out = (float*)d_out;

    int B = in_sizes[0] / 9;
    if (B > MAXB) B = MAXB;

    wprep_kernel<<<(26 * 2048 + 255) / 256, 256>>>(W1, W2, W3, W4, W5, emb, traj, b1);

    cudaFuncSetAttribute(mlp_mma_kernel, cudaFuncAttributeMaxDynamicSharedMemorySize, SMEM_TOTAL);
    int nblk = (B + TILE_M - 1) / TILE_M;
    mlp_mma_kernel<<<nblk, THREADS, SMEM_TOTAL>>>(F, C, b2, b3, b4, b5, out, B);
}

// round 14
// speedup vs baseline: 1.3496x; 1.0048x over previous
#include <cuda_runtime.h>
#include <cuda_bf16.h>
#include <math.h>
#include <stdint.h>

#define MAXB    262144
#define TILE_M  64
#define THREADS 256
#define EPSF    1e-6f

#define NFINE    51            // 16KB fine chunks, linear 0..50
#define FINE_U4  1024
#define SA_HI    0
#define SA_LO    32768
#define SCRATCH  65536         // feats [64][33] early; L5 partials (32KB) late
#define SMEM_TOTAL (SCRATCH + 32768)       // 98304 -> 2 CTAs/SM

// ---------------- device globals ----------------
__device__ __align__(128) uint4 g_wimg[26 * 2048];   // b-frag weight image
__device__ float g_c1[256];                          // b1 + latent @ W1[25:153]
__device__ float g_R[MAXB * 9];                      // polar rotations

// ---------------- helpers ----------------
__device__ __forceinline__ uint32_t packbf2(float lo, float hi) {
    uint32_t r;
    asm("cvt.rn.bf16x2.f32 %0, %1, %2;" : "=r"(r) : "f"(hi), "f"(lo));
    return r;
}

__device__ __forceinline__ void split2(float a, float b, uint32_t& h, uint32_t& l) {
    h = packbf2(a, b);
    float ha = __uint_as_float(h << 16);
    float hb = __uint_as_float(h & 0xffff0000u);
    l = packbf2(a - ha, b - hb);
}

__device__ __forceinline__ void mma_bf16(float* d, const uint4& a, uint32_t b0, uint32_t b1) {
    asm volatile("mma.sync.aligned.m16n8k16.row.col.f32.bf16.bf16.f32 "
        "{%0,%1,%2,%3}, {%4,%5,%6,%7}, {%8,%9}, {%0,%1,%2,%3};"
        : "+f"(d[0]), "+f"(d[1]), "+f"(d[2]), "+f"(d[3])
        : "r"(a.x), "r"(a.y), "r"(a.z), "r"(a.w), "r"(b0), "r"(b1));
}

__device__ __forceinline__ float gelu_exact(float x) {
    return 0.5f * x * (1.0f + erff(x * 0.70710678118654752f));
}

// ---------------- prep kernel: weight image + c1 fold (unchanged) ----------
__global__ void wprep_kernel(const float* __restrict__ W1, const float* __restrict__ W2,
                             const float* __restrict__ W3, const float* __restrict__ W4,
                             const float* __restrict__ W5,
                             const float* __restrict__ emb, const int* __restrict__ traj,
                             const float* __restrict__ b1) {
    if (blockIdx.x == 0) {
        int n = threadIdx.x;               // 256 threads
        const float* lat = emb + traj[0] * 128;
        float s = b1[n];
        #pragma unroll 4
        for (int d = 0; d < 128; ++d)
            s = fmaf(__ldg(lat + d), __ldg(W1 + (25 + d) * 256 + n), s);
        g_c1[n] = s;
    }

    int e = blockIdx.x * blockDim.x + threadIdx.x;
    if (e >= 26 * 2048) return;
    int gc = e >> 11, within = e & 2047;
    const float* W; int Kreal, Nreal, ld, kt, nt, lane;
    if (gc == 0) {
        W = W1; Kreal = 25; Nreal = 256; ld = 256;
        kt = within >> 10; int rem = within & 1023; nt = rem >> 5; lane = rem & 31;
    } else if (gc <= 8) {
        W = W2; Kreal = 256; Nreal = 256; ld = 256;
        kt = (gc - 1) * 2 + (within >> 10); int rem = within & 1023; nt = rem >> 5; lane = rem & 31;
    } else if (gc <= 16) {
        W = W3; Kreal = 256; Nreal = 256; ld = 256;
        kt = (gc - 9) * 2 + (within >> 10); int rem = within & 1023; nt = rem >> 5; lane = rem & 31;
    } else if (gc <= 24) {
        W = W4; Kreal = 256; Nreal = 256; ld = 256;
        kt = (gc - 17) * 2 + (within >> 10); int rem = within & 1023; nt = rem >> 5; lane = rem & 31;
    } else {
        if (within >= 1024) { g_wimg[e] = make_uint4(0u, 0u, 0u, 0u); return; }
        W = W5; Kreal = 256; Nreal = 9; ld = 9;
        kt = within >> 6; nt = (within >> 5) & 1; lane = within & 31;
    }
    int q = lane & 3, n = nt * 8 + (lane >> 2);
    int k0 = kt * 16 + 2 * q;
    float v00 = (k0     < Kreal && n < Nreal) ? W[(size_t)(k0    ) * ld + n] : 0.f;
    float v01 = (k0 + 1 < Kreal && n < Nreal) ? W[(size_t)(k0 + 1) * ld + n] : 0.f;
    float v10 = (k0 + 8 < Kreal && n < Nreal) ? W[(size_t)(k0 + 8) * ld + n] : 0.f;
    float v11 = (k0 + 9 < Kreal && n < Nreal) ? W[(size_t)(k0 + 9) * ld + n] : 0.f;
    uint4 o;
    uint32_t h, l;
    split2(v00, v01, h, l); o.x = h; o.z = l;
    split2(v10, v11, h, l); o.y = h; o.w = l;
    g_wimg[e] = o;
}

// ---------------- main kernel: register-streamed B, GELU in MMA shadow ------
__global__ void __launch_bounds__(THREADS, 2)
mlp_mma_kernel(const float* __restrict__ Fg, const float* __restrict__ Cg,
               const float* __restrict__ b2, const float* __restrict__ b3,
               const float* __restrict__ b4, const float* __restrict__ b5,
               float* __restrict__ outg, int B)
{
    extern __shared__ __align__(1024) char smem[];
    const int tid  = threadIdx.x;
    const int lane = tid & 31;
    const int w    = tid >> 5;       // warp id 0..7: n-slice [32w, 32w+32)
    const int q    = lane & 3;
    const int blockRow = blockIdx.x * TILE_M;

    uint4* sAhi = (uint4*)(smem + SA_HI);
    uint4* sAlo = (uint4*)(smem + SA_LO);

    // this thread's B words: g_wimg[g*1024 + (w*4+j)*32 + lane]
    const uint4* srcPtr = g_wimg + (w * 4) * 32 + lane;

    // preload chunk 0 into bc (covered by the front-end below)
    uint4 bc[4], bn[4];
    #pragma unroll
    for (int j = 0; j < 4; ++j) bc[j] = __ldg(srcPtr + j * 32);
    srcPtr += FINE_U4;      // now points at chunk 1

    // ---------------- front-end (threads 0-63; feats -> scratch) -------------
    float* feats_s = (float*)(smem + SCRATCH);   // [64][33]
    if (tid < TILE_M) {
        int ig = blockRow + tid; if (ig >= B) ig = B - 1;
        float f[9], r[9];
        #pragma unroll
        for (int k = 0; k < 9; ++k) { f[k] = Fg[(size_t)ig * 9 + k]; r[k] = f[k]; }
        #pragma unroll
        for (int it = 0; it < 5; ++it) {
            float c00 = r[4]*r[8]-r[5]*r[7], c01 = r[5]*r[6]-r[3]*r[8], c02 = r[3]*r[7]-r[4]*r[6];
            float c10 = r[2]*r[7]-r[1]*r[8], c11 = r[0]*r[8]-r[2]*r[6], c12 = r[1]*r[6]-r[0]*r[7];
            float c20 = r[1]*r[5]-r[2]*r[4], c21 = r[2]*r[3]-r[0]*r[5], c22 = r[0]*r[4]-r[1]*r[3];
            float det = r[0]*c00 + r[1]*c01 + r[2]*c02;
            float ad  = fmaxf(fabsf(det), 1e-30f);
            float mu  = rcbrtf(ad);
            float s2  = 0.5f * mu;
            float s3  = 0.5f / (mu * det);
            float n0=s2*r[0]+s3*c00, n1=s2*r[1]+s3*c01, n2=s2*r[2]+s3*c02;
            float n3=s2*r[3]+s3*c10, n4=s2*r[4]+s3*c11, n5=s2*r[5]+s3*c12;
            float n6=s2*r[6]+s3*c20, n7=s2*r[7]+s3*c21, n8=s2*r[8]+s3*c22;
            r[0]=n0;r[1]=n1;r[2]=n2;r[3]=n3;r[4]=n4;r[5]=n5;r[6]=n6;r[7]=n7;r[8]=n8;
        }
        float a00=f[0]*f[0]+f[3]*f[3]+f[6]*f[6];
        float a01=f[0]*f[1]+f[3]*f[4]+f[6]*f[7];
        float a02=f[0]*f[2]+f[3]*f[5]+f[6]*f[8];
        float a11=f[1]*f[1]+f[4]*f[4]+f[7]*f[7];
        float a12=f[1]*f[2]+f[4]*f[5]+f[7]*f[8];
        float a22=f[2]*f[2]+f[5]*f[5]+f[8]*f[8];
        float qv = (a00+a11+a22)*(1.0f/3.0f);
        float d0 = a00-qv, d1 = a11-qv, d2 = a22-qv;
        float p2 = d0*d0+d1*d1+d2*d2+2.0f*(a01*a01+a02*a02+a12*a12);
        float e1,e2,e3;
        if (p2 < 1e-18f) { e1=e2=e3=qv; }
        else {
            float p = sqrtf(p2*(1.0f/6.0f)), invp = 1.0f/p;
            float b00=d0*invp,b11=d1*invp,b22=d2*invp;
            float b01=a01*invp,b02=a02*invp,b12=a12*invp;
            float detB = b00*(b11*b22-b12*b12)-b01*(b01*b22-b12*b02)+b02*(b01*b12-b11*b02);
            float rr = fminf(fmaxf(0.5f*detB,-1.0f),1.0f);
            float phi = acosf(rr)*(1.0f/3.0f);
            e1 = qv+2.0f*p*cosf(phi);
            e3 = qv+2.0f*p*cosf(phi+2.09439510239319549f);
            e2 = 3.0f*qv-e1-e3;
        }
        float detF = f[0]*(f[4]*f[8]-f[5]*f[7]) - f[1]*(f[3]*f[8]-f[5]*f[6]) + f[2]*(f[3]*f[7]-f[4]*f[6]);
        float f00c = fmaxf(f[0], EPSF);
        float ft[32];
        ft[0]=sqrtf(fmaxf(e1,0.f))-1.f; ft[1]=sqrtf(fmaxf(e2,0.f))-1.f; ft[2]=sqrtf(fmaxf(e3,0.f))-1.f;
        ft[3]=a00-1.f; ft[4]=a01; ft[5]=a02;
        ft[6]=a01; ft[7]=a11-1.f; ft[8]=a12;
        ft[9]=a02; ft[10]=a12; ft[11]=a22-1.f;
        ft[12]=detF-1.f; ft[13]=logf(detF)-1.f;
        ft[14]=f00c-1.f; ft[15]=logf(f00c)-1.f;
        #pragma unroll
        for (int j = 0; j < 9; ++j) ft[16+j] = Cg[(size_t)ig*9+j];
        #pragma unroll
        for (int j = 25; j < 32; ++j) ft[j] = 0.0f;
        #pragma unroll
        for (int k = 0; k < 32; ++k) feats_s[tid * 33 + k] = ft[k];
        #pragma unroll
        for (int k = 0; k < 9; ++k) g_R[(size_t)ig * 9 + k] = r[k];
    }
    __syncthreads();

    // build L1 A-frags: warp w -> (mtg = w>>1, kt = w&1)
    {
        int mtg = w >> 1;
        int kt  = w & 1;
        int r0 = mtg * 16 + (lane >> 2);
        int k0 = kt * 16 + 2 * q;
        uint4 h4, l4; uint32_t hh, ll;
        split2(feats_s[r0*33 + k0],       feats_s[r0*33 + k0 + 1],       hh, ll); h4.x = hh; l4.x = ll;
        split2(feats_s[(r0+8)*33 + k0],   feats_s[(r0+8)*33 + k0 + 1],   hh, ll); h4.y = hh; l4.y = ll;
        split2(feats_s[r0*33 + k0 + 8],   feats_s[r0*33 + k0 + 9],       hh, ll); h4.z = hh; l4.z = ll;
        split2(feats_s[(r0+8)*33 + k0+8], feats_s[(r0+8)*33 + k0 + 9],   hh, ll); h4.w = hh; l4.w = ll;
        sAhi[(mtg * 16 + kt) * 32 + lane] = h4;
        sAlo[(mtg * 16 + kt) * 32 + lane] = l4;
    }
    __syncthreads();   // feats reads + L1 A-frags complete before loop

    // ---------------- layer loop: 2x-unrolled, alternating B buffers ---------
    float acc[4][4][4];
    #pragma unroll
    for (int m = 0; m < 4; ++m)
        #pragma unroll
        for (int t = 0; t < 4; ++t)
            #pragma unroll
            for (int j = 0; j < 4; ++j) acc[m][t][j] = 0.0f;

    const float* biasA[4] = {g_c1, b2, b3, b4};

    for (int L = 0; L < 4; ++L) {
        const int nc = (L == 0) ? 2 : 16;       // even for all layers
        const float* bias = biasA[L];
        for (int kt = 0; kt < nc; kt += 2) {
            // ---- even epoch: consume bc, prefetch next chunk into bn --------
            #pragma unroll
            for (int j = 0; j < 4; ++j) bn[j] = __ldg(srcPtr + j * 32);
            srcPtr += FINE_U4;
            #pragma unroll
            for (int m = 0; m < 4; ++m) {
                uint4 ah = sAhi[(m * 16 + kt) * 32 + lane];
                uint4 al = sAlo[(m * 16 + kt) * 32 + lane];
                #pragma unroll
                for (int j = 0; j < 4; ++j) mma_bf16(acc[m][j], ah, bc[j].x, bc[j].y);
                #pragma unroll
                for (int j = 0; j < 4; ++j) mma_bf16(acc[m][j], al, bc[j].x, bc[j].y);
                #pragma unroll
                for (int j = 0; j < 4; ++j) mma_bf16(acc[m][j], ah, bc[j].z, bc[j].w);
            }
            // ---- odd epoch: consume bn, prefetch next chunk into bc ---------
            // (final odd epoch of L4 prefetches chunk 50 = L5 weights into bc)
            #pragma unroll
            for (int j = 0; j < 4; ++j) bc[j] = __ldg(srcPtr + j * 32);
            srcPtr += FINE_U4;
            #pragma unroll
            for (int m = 0; m < 4; ++m) {
                uint4 ah = sAhi[(m * 16 + kt + 1) * 32 + lane];
                uint4 al = sAlo[(m * 16 + kt + 1) * 32 + lane];
                #pragma unroll
                for (int j = 0; j < 4; ++j) mma_bf16(acc[m][j], ah, bn[j].x, bn[j].y);
                #pragma unroll
                for (int j = 0; j < 4; ++j) mma_bf16(acc[m][j], al, bn[j].x, bn[j].y);
                #pragma unroll
                for (int j = 0; j < 4; ++j) mma_bf16(acc[m][j], ah, bn[j].z, bn[j].w);
            }
        }

        // -------- layer boundary ---------------------------------------------
        // GELU computed BEFORE the barrier (tensor-idle shadow of lagging
        // warps); in-place into acc. Post-barrier: split + STS only.
        {
            float bb0[2][2], bb1[2][2];  // hoisted bias: [tb][u]
            #pragma unroll
            for (int tb = 0; tb < 2; ++tb)
                #pragma unroll
                for (int u = 0; u < 2; ++u) {
                    int t = 2 * tb + u;
                    bb0[tb][u] = __ldg(bias + w * 32 + t * 8 + 2 * q);
                    bb1[tb][u] = __ldg(bias + w * 32 + t * 8 + 2 * q + 1);
                }
            #pragma unroll
            for (int m = 0; m < 4; ++m)
                #pragma unroll
                for (int tb = 0; tb < 2; ++tb)
                    #pragma unroll
                    for (int u = 0; u < 2; ++u) {
                        int t = 2 * tb + u;
                        acc[m][t][0] = gelu_exact(acc[m][t][0] + bb0[tb][u]);
                        acc[m][t][1] = gelu_exact(acc[m][t][1] + bb1[tb][u]);
                        acc[m][t][2] = gelu_exact(acc[m][t][2] + bb0[tb][u]);
                        acc[m][t][3] = gelu_exact(acc[m][t][3] + bb1[tb][u]);
                    }
        }
        __syncthreads();             // all warps done READING this layer's A-frags
        #pragma unroll
        for (int m = 0; m < 4; ++m) {
            #pragma unroll
            for (int tb = 0; tb < 2; ++tb) {
                int t0 = 2 * tb, t1 = 2 * tb + 1;
                uint4 h4, l4; uint32_t hh, ll;
                split2(acc[m][t0][0], acc[m][t0][1], hh, ll); h4.x = hh; l4.x = ll;
                split2(acc[m][t0][2], acc[m][t0][3], hh, ll); h4.y = hh; l4.y = ll;
                split2(acc[m][t1][0], acc[m][t1][1], hh, ll); h4.z = hh; l4.z = ll;
                split2(acc[m][t1][2], acc[m][t1][3], hh, ll); h4.w = hh; l4.w = ll;
                acc[m][t0][0] = 0.f; acc[m][t0][1] = 0.f; acc[m][t0][2] = 0.f; acc[m][t0][3] = 0.f;
                acc[m][t1][0] = 0.f; acc[m][t1][1] = 0.f; acc[m][t1][2] = 0.f; acc[m][t1][3] = 0.f;
                int kt_out = w * 2 + tb;
                sAhi[(m * 16 + kt_out) * 32 + lane] = h4;
                sAlo[(m * 16 + kt_out) * 32 + lane] = l4;
            }
        }
        __syncthreads();             // new A-frags visible
    }

    // ---------------- layer 5: bc holds chunk 50 -----------------------------
    // kt in {2w, 2w+1} via j = 2u + nt
    {
        #pragma unroll
        for (int u = 0; u < 2; ++u) {
            int kt = 2 * w + u;
            #pragma unroll
            for (int m = 0; m < 4; ++m) {
                uint4 ah = sAhi[(m * 16 + kt) * 32 + lane];
                uint4 al = sAlo[(m * 16 + kt) * 32 + lane];
                #pragma unroll
                for (int nt = 0; nt < 2; ++nt) {
                    uint4 b = bc[2 * u + nt];
                    mma_bf16(acc[m][nt], ah, b.x, b.y);
                    mma_bf16(acc[m][nt], al, b.x, b.y);
                    mma_bf16(acc[m][nt], ah, b.z, b.w);
                }
            }
        }
        // write per-warp partial [64 rows x 16 cols] into scratch
        float* part = (float*)(smem + SCRATCH) + w * 1024;
        #pragma unroll
        for (int m = 0; m < 4; ++m)
            #pragma unroll
            for (int nt = 0; nt < 2; ++nt) {
                int r0 = m * 16 + (lane >> 2);
                int c0 = nt * 8 + 2 * q;
                part[r0 * 16 + c0]           = acc[m][nt][0];
                part[r0 * 16 + c0 + 1]       = acc[m][nt][1];
                part[(r0 + 8) * 16 + c0]     = acc[m][nt][2];
                part[(r0 + 8) * 16 + c0 + 1] = acc[m][nt][3];
            }
    }
    __syncthreads();

    // ---------------- final epilogue: reduce 8 partials, stress --------------
    if (tid < TILE_M) {
        int ig = blockRow + tid;
        if (ig < B) {
            const float* part = (const float*)(smem + SCRATCH);
            float x[9];
            #pragma unroll
            for (int n = 0; n < 9; ++n) {
                float s = __ldg(b5 + n);
                #pragma unroll
                for (int ww = 0; ww < 8; ++ww)
                    s += part[ww * 1024 + tid * 16 + n];
                x[n] = s;
            }
            float xs[9];
            xs[0]=x[0]; xs[4]=x[4]; xs[8]=x[8];
            xs[1]=xs[3]=0.5f*(x[1]+x[3]);
            xs[2]=xs[6]=0.5f*(x[2]+x[6]);
            xs[5]=xs[7]=0.5f*(x[5]+x[7]);
            float R[9], Ff[9], P[9];
            #pragma unroll
            for (int k = 0; k < 9; ++k) R[k]  = g_R[(size_t)ig * 9 + k];
            #pragma unroll
            for (int k = 0; k < 9; ++k) Ff[k] = Fg[(size_t)ig * 9 + k];
            #pragma unroll
            for (int rI = 0; rI < 3; ++rI)
                #pragma unroll
                for (int cI = 0; cI < 3; ++cI)
                    P[rI*3+cI] = R[rI*3+0]*xs[0*3+cI] + R[rI*3+1]*xs[1*3+cI] + R[rI*3+2]*xs[2*3+cI];
            #pragma unroll
            for (int rI = 0; rI < 3; ++rI)
                #pragma unroll
                for (int cI = 0; cI < 3; ++cI)
                    outg[(size_t)ig*9 + rI*3 + cI] =
                        P[rI*3+0]*Ff[cI*3+0] + P[rI*3+1]*Ff[cI*3+1] + P[rI*3+2]*Ff[cI*3+2];
        }
    }
}

// ---------------- launch ----------------
extern "C" void kernel_launch(void* const* d_in, const int* in_sizes, int n_in,
                              void* d_out, int out_size) {
    const float* F    = (const float*)d_in[0];
    const float* C    = (const float*)d_in[1];
    const float* emb  = (const float*)d_in[2];
    const int*   traj = (const int*)  d_in[3];
    const float* W1 = (const float*)d_in[4];
    const float* b1 = (const float*)d_in[5];
    const float* W2 = (const float*)d_in[6];
    const float* b2 = (const float*)d_in[7];
    const float* W3 = (const float*)d_in[8];
    const float* b3 = (const float*)d_in[9];
    const float* W4 = (const float*)d_in[10];
    const float* b4 = (const float*)d_in[11];
    const float* W5 = (const float*)d_in[12];
    const float* b5 = (const float*)d_in[13];
    float* out = (float*)d_out;

    int B = in_sizes[0] / 9;
    if (B > MAXB) B = MAXB;

    wprep_kernel<<<(26 * 2048 + 255) / 256, 256>>>(W1, W2, W3, W4, W5, emb, traj, b1);

    cudaFuncSetAttribute(mlp_mma_kernel, cudaFuncAttributeMaxDynamicSharedMemorySize, SMEM_TOTAL);
    int nblk = (B + TILE_M - 1) / TILE_M;
    mlp_mma_kernel<<<nblk, THREADS, SMEM_TOTAL>>>(F, C, b2, b3, b4, b5, out, B);
}

// round 15
// speedup vs baseline: 1.3639x; 1.0106x over previous
#include <cuda_runtime.h>
#include <cuda_bf16.h>
#include <math.h>
#include <stdint.h>

#define MAXB    262144
#define TILE_M  64
#define THREADS 256
#define EPSF    1e-6f

#define NFINE    51            // 16KB fine chunks, linear 0..50
#define FINE_U4  1024
#define SA_HI    0
#define SA_LO    32768
#define SCRATCH  65536         // feats [64][33] early; L5 partials (32KB) late
#define RF_OFF   (SCRATCH + 32768)         // staged R (576 f) + F (576 f)
#define SMEM_TOTAL (RF_OFF + 4608)         // 102912 -> still 2 CTAs/SM

// ---------------- device globals ----------------
__device__ __align__(128) uint4 g_wimg[26 * 2048];   // b-frag weight image
__device__ float g_c1[256];                          // b1 + latent @ W1[25:153]
__device__ float g_R[MAXB * 9];                      // polar rotations

// ---------------- helpers ----------------
__device__ __forceinline__ uint32_t packbf2(float lo, float hi) {
    uint32_t r;
    asm("cvt.rn.bf16x2.f32 %0, %1, %2;" : "=r"(r) : "f"(hi), "f"(lo));
    return r;
}

__device__ __forceinline__ void split2(float a, float b, uint32_t& h, uint32_t& l) {
    h = packbf2(a, b);
    float ha = __uint_as_float(h << 16);
    float hb = __uint_as_float(h & 0xffff0000u);
    l = packbf2(a - ha, b - hb);
}

__device__ __forceinline__ void mma_bf16(float* d, const uint4& a, uint32_t b0, uint32_t b1) {
    asm volatile("mma.sync.aligned.m16n8k16.row.col.f32.bf16.bf16.f32 "
        "{%0,%1,%2,%3}, {%4,%5,%6,%7}, {%8,%9}, {%0,%1,%2,%3};"
        : "+f"(d[0]), "+f"(d[1]), "+f"(d[2]), "+f"(d[3])
        : "r"(a.x), "r"(a.y), "r"(a.z), "r"(a.w), "r"(b0), "r"(b1));
}

__device__ __forceinline__ float gelu_exact(float x) {
    return 0.5f * x * (1.0f + erff(x * 0.70710678118654752f));
}

// ---------------- prep kernel: weight image + c1 fold (unchanged) ----------
__global__ void wprep_kernel(const float* __restrict__ W1, const float* __restrict__ W2,
                             const float* __restrict__ W3, const float* __restrict__ W4,
                             const float* __restrict__ W5,
                             const float* __restrict__ emb, const int* __restrict__ traj,
                             const float* __restrict__ b1) {
    if (blockIdx.x == 0) {
        int n = threadIdx.x;               // 256 threads
        const float* lat = emb + traj[0] * 128;
        float s = b1[n];
        #pragma unroll 4
        for (int d = 0; d < 128; ++d)
            s = fmaf(__ldg(lat + d), __ldg(W1 + (25 + d) * 256 + n), s);
        g_c1[n] = s;
    }

    int e = blockIdx.x * blockDim.x + threadIdx.x;
    if (e >= 26 * 2048) return;
    int gc = e >> 11, within = e & 2047;
    const float* W; int Kreal, Nreal, ld, kt, nt, lane;
    if (gc == 0) {
        W = W1; Kreal = 25; Nreal = 256; ld = 256;
        kt = within >> 10; int rem = within & 1023; nt = rem >> 5; lane = rem & 31;
    } else if (gc <= 8) {
        W = W2; Kreal = 256; Nreal = 256; ld = 256;
        kt = (gc - 1) * 2 + (within >> 10); int rem = within & 1023; nt = rem >> 5; lane = rem & 31;
    } else if (gc <= 16) {
        W = W3; Kreal = 256; Nreal = 256; ld = 256;
        kt = (gc - 9) * 2 + (within >> 10); int rem = within & 1023; nt = rem >> 5; lane = rem & 31;
    } else if (gc <= 24) {
        W = W4; Kreal = 256; Nreal = 256; ld = 256;
        kt = (gc - 17) * 2 + (within >> 10); int rem = within & 1023; nt = rem >> 5; lane = rem & 31;
    } else {
        if (within >= 1024) { g_wimg[e] = make_uint4(0u, 0u, 0u, 0u); return; }
        W = W5; Kreal = 256; Nreal = 9; ld = 9;
        kt = within >> 6; nt = (within >> 5) & 1; lane = within & 31;
    }
    int q = lane & 3, n = nt * 8 + (lane >> 2);
    int k0 = kt * 16 + 2 * q;
    float v00 = (k0     < Kreal && n < Nreal) ? W[(size_t)(k0    ) * ld + n] : 0.f;
    float v01 = (k0 + 1 < Kreal && n < Nreal) ? W[(size_t)(k0 + 1) * ld + n] : 0.f;
    float v10 = (k0 + 8 < Kreal && n < Nreal) ? W[(size_t)(k0 + 8) * ld + n] : 0.f;
    float v11 = (k0 + 9 < Kreal && n < Nreal) ? W[(size_t)(k0 + 9) * ld + n] : 0.f;
    uint4 o;
    uint32_t h, l;
    split2(v00, v01, h, l); o.x = h; o.z = l;
    split2(v10, v11, h, l); o.y = h; o.w = l;
    g_wimg[e] = o;
}

// ---------------- main kernel -----------------------------------------------
__global__ void __launch_bounds__(THREADS, 2)
mlp_mma_kernel(const float* __restrict__ Fg, const float* __restrict__ Cg,
               const float* __restrict__ b2, const float* __restrict__ b3,
               const float* __restrict__ b4, const float* __restrict__ b5,
               float* __restrict__ outg, int B)
{
    extern __shared__ __align__(1024) char smem[];
    const int tid  = threadIdx.x;
    const int lane = tid & 31;
    const int w    = tid >> 5;       // warp id 0..7: n-slice [32w, 32w+32)
    const int q    = lane & 3;
    const int blockRow = blockIdx.x * TILE_M;

    uint4* sAhi = (uint4*)(smem + SA_HI);
    uint4* sAlo = (uint4*)(smem + SA_LO);

    // this thread's B words: g_wimg[g*1024 + (w*4+j)*32 + lane]
    const uint4* srcPtr = g_wimg + (w * 4) * 32 + lane;

    // preload chunk 0 into bc (covered by the front-end below)
    uint4 bc[4], bn[4];
    #pragma unroll
    for (int j = 0; j < 4; ++j) bc[j] = __ldg(srcPtr + j * 32);
    srcPtr += FINE_U4;      // now points at chunk 1

    // ---------------- front-end (threads 0-63; feats -> scratch) -------------
    float* feats_s = (float*)(smem + SCRATCH);   // [64][33]
    if (tid < TILE_M) {
        int ig = blockRow + tid; if (ig >= B) ig = B - 1;
        float f[9], r[9];
        #pragma unroll
        for (int k = 0; k < 9; ++k) { f[k] = Fg[(size_t)ig * 9 + k]; r[k] = f[k]; }
        #pragma unroll
        for (int it = 0; it < 5; ++it) {
            float c00 = r[4]*r[8]-r[5]*r[7], c01 = r[5]*r[6]-r[3]*r[8], c02 = r[3]*r[7]-r[4]*r[6];
            float c10 = r[2]*r[7]-r[1]*r[8], c11 = r[0]*r[8]-r[2]*r[6], c12 = r[1]*r[6]-r[0]*r[7];
            float c20 = r[1]*r[5]-r[2]*r[4], c21 = r[2]*r[3]-r[0]*r[5], c22 = r[0]*r[4]-r[1]*r[3];
            float det = r[0]*c00 + r[1]*c01 + r[2]*c02;
            float ad  = fmaxf(fabsf(det), 1e-30f);
            float mu  = rcbrtf(ad);
            float s2  = 0.5f * mu;
            float s3  = 0.5f / (mu * det);
            float n0=s2*r[0]+s3*c00, n1=s2*r[1]+s3*c01, n2=s2*r[2]+s3*c02;
            float n3=s2*r[3]+s3*c10, n4=s2*r[4]+s3*c11, n5=s2*r[5]+s3*c12;
            float n6=s2*r[6]+s3*c20, n7=s2*r[7]+s3*c21, n8=s2*r[8]+s3*c22;
            r[0]=n0;r[1]=n1;r[2]=n2;r[3]=n3;r[4]=n4;r[5]=n5;r[6]=n6;r[7]=n7;r[8]=n8;
        }
        float a00=f[0]*f[0]+f[3]*f[3]+f[6]*f[6];
        float a01=f[0]*f[1]+f[3]*f[4]+f[6]*f[7];
        float a02=f[0]*f[2]+f[3]*f[5]+f[6]*f[8];
        float a11=f[1]*f[1]+f[4]*f[4]+f[7]*f[7];
        float a12=f[1]*f[2]+f[4]*f[5]+f[7]*f[8];
        float a22=f[2]*f[2]+f[5]*f[5]+f[8]*f[8];
        float qv = (a00+a11+a22)*(1.0f/3.0f);
        float d0 = a00-qv, d1 = a11-qv, d2 = a22-qv;
        float p2 = d0*d0+d1*d1+d2*d2+2.0f*(a01*a01+a02*a02+a12*a12);
        float e1,e2,e3;
        if (p2 < 1e-18f) { e1=e2=e3=qv; }
        else {
            float p = sqrtf(p2*(1.0f/6.0f)), invp = 1.0f/p;
            float b00=d0*invp,b11=d1*invp,b22=d2*invp;
            float b01=a01*invp,b02=a02*invp,b12=a12*invp;
            float detB = b00*(b11*b22-b12*b12)-b01*(b01*b22-b12*b02)+b02*(b01*b12-b11*b02);
            float rr = fminf(fmaxf(0.5f*detB,-1.0f),1.0f);
            float phi = acosf(rr)*(1.0f/3.0f);
            e1 = qv+2.0f*p*cosf(phi);
            e3 = qv+2.0f*p*cosf(phi+2.09439510239319549f);
            e2 = 3.0f*qv-e1-e3;
        }
        float detF = f[0]*(f[4]*f[8]-f[5]*f[7]) - f[1]*(f[3]*f[8]-f[5]*f[6]) + f[2]*(f[3]*f[7]-f[4]*f[6]);
        float f00c = fmaxf(f[0], EPSF);
        float ft[32];
        ft[0]=sqrtf(fmaxf(e1,0.f))-1.f; ft[1]=sqrtf(fmaxf(e2,0.f))-1.f; ft[2]=sqrtf(fmaxf(e3,0.f))-1.f;
        ft[3]=a00-1.f; ft[4]=a01; ft[5]=a02;
        ft[6]=a01; ft[7]=a11-1.f; ft[8]=a12;
        ft[9]=a02; ft[10]=a12; ft[11]=a22-1.f;
        ft[12]=detF-1.f; ft[13]=logf(detF)-1.f;
        ft[14]=f00c-1.f; ft[15]=logf(f00c)-1.f;
        #pragma unroll
        for (int j = 0; j < 9; ++j) ft[16+j] = Cg[(size_t)ig*9+j];
        #pragma unroll
        for (int j = 25; j < 32; ++j) ft[j] = 0.0f;
        #pragma unroll
        for (int k = 0; k < 32; ++k) feats_s[tid * 33 + k] = ft[k];
        #pragma unroll
        for (int k = 0; k < 9; ++k) g_R[(size_t)ig * 9 + k] = r[k];
    }
    __syncthreads();

    // build L1 A-frags: warp w -> (mtg = w>>1, kt = w&1)
    {
        int mtg = w >> 1;
        int kt  = w & 1;
        int r0 = mtg * 16 + (lane >> 2);
        int k0 = kt * 16 + 2 * q;
        uint4 h4, l4; uint32_t hh, ll;
        split2(feats_s[r0*33 + k0],       feats_s[r0*33 + k0 + 1],       hh, ll); h4.x = hh; l4.x = ll;
        split2(feats_s[(r0+8)*33 + k0],   feats_s[(r0+8)*33 + k0 + 1],   hh, ll); h4.y = hh; l4.y = ll;
        split2(feats_s[r0*33 + k0 + 8],   feats_s[r0*33 + k0 + 9],       hh, ll); h4.z = hh; l4.z = ll;
        split2(feats_s[(r0+8)*33 + k0+8], feats_s[(r0+8)*33 + k0 + 9],   hh, ll); h4.w = hh; l4.w = ll;
        sAhi[(mtg * 16 + kt) * 32 + lane] = h4;
        sAlo[(mtg * 16 + kt) * 32 + lane] = l4;
    }
    __syncthreads();   // feats reads + L1 A-frags complete before loop

    // ---------------- layer loop: 2x-unrolled, alternating B buffers ---------
    float acc[4][4][4];
    #pragma unroll
    for (int m = 0; m < 4; ++m)
        #pragma unroll
        for (int t = 0; t < 4; ++t)
            #pragma unroll
            for (int j = 0; j < 4; ++j) acc[m][t][j] = 0.0f;

    const float* biasA[4] = {g_c1, b2, b3, b4};

    for (int L = 0; L < 4; ++L) {
        const int nc = (L == 0) ? 2 : 16;       // even for all layers
        const float* bias = biasA[L];
        for (int kt = 0; kt < nc; kt += 2) {
            // ---- even epoch: consume bc; prefetch into bn AFTER 24 MMAs -----
            #pragma unroll
            for (int m = 0; m < 4; ++m) {
                if (m == 2) {
                    #pragma unroll
                    for (int j = 0; j < 4; ++j) bn[j] = __ldg(srcPtr + j * 32);
                    srcPtr += FINE_U4;
                }
                uint4 ah = sAhi[(m * 16 + kt) * 32 + lane];
                uint4 al = sAlo[(m * 16 + kt) * 32 + lane];
                #pragma unroll
                for (int j = 0; j < 4; ++j) mma_bf16(acc[m][j], ah, bc[j].x, bc[j].y);
                #pragma unroll
                for (int j = 0; j < 4; ++j) mma_bf16(acc[m][j], al, bc[j].x, bc[j].y);
                #pragma unroll
                for (int j = 0; j < 4; ++j) mma_bf16(acc[m][j], ah, bc[j].z, bc[j].w);
            }
            // ---- odd epoch: consume bn; prefetch into bc AFTER 24 MMAs ------
            // (final odd epoch of L4 prefetches chunk 50 = L5 weights into bc)
            #pragma unroll
            for (int m = 0; m < 4; ++m) {
                if (m == 2) {
                    #pragma unroll
                    for (int j = 0; j < 4; ++j) bc[j] = __ldg(srcPtr + j * 32);
                    srcPtr += FINE_U4;
                }
                uint4 ah = sAhi[(m * 16 + kt + 1) * 32 + lane];
                uint4 al = sAlo[(m * 16 + kt + 1) * 32 + lane];
                #pragma unroll
                for (int j = 0; j < 4; ++j) mma_bf16(acc[m][j], ah, bn[j].x, bn[j].y);
                #pragma unroll
                for (int j = 0; j < 4; ++j) mma_bf16(acc[m][j], al, bn[j].x, bn[j].y);
                #pragma unroll
                for (int j = 0; j < 4; ++j) mma_bf16(acc[m][j], ah, bn[j].z, bn[j].w);
            }
        }

        // -------- layer boundary ---------------------------------------------
        // GELU before the barrier (tensor-idle shadow); split+STS after.
        {
            float bb0[2][2], bb1[2][2];  // hoisted bias: [tb][u]
            #pragma unroll
            for (int tb = 0; tb < 2; ++tb)
                #pragma unroll
                for (int u = 0; u < 2; ++u) {
                    int t = 2 * tb + u;
                    bb0[tb][u] = __ldg(bias + w * 32 + t * 8 + 2 * q);
                    bb1[tb][u] = __ldg(bias + w * 32 + t * 8 + 2 * q + 1);
                }
            #pragma unroll
            for (int m = 0; m < 4; ++m)
                #pragma unroll
                for (int tb = 0; tb < 2; ++tb)
                    #pragma unroll
                    for (int u = 0; u < 2; ++u) {
                        int t = 2 * tb + u;
                        acc[m][t][0] = gelu_exact(acc[m][t][0] + bb0[tb][u]);
                        acc[m][t][1] = gelu_exact(acc[m][t][1] + bb1[tb][u]);
                        acc[m][t][2] = gelu_exact(acc[m][t][2] + bb0[tb][u]);
                        acc[m][t][3] = gelu_exact(acc[m][t][3] + bb1[tb][u]);
                    }
        }
        __syncthreads();             // all warps done READING this layer's A-frags
        #pragma unroll
        for (int m = 0; m < 4; ++m) {
            #pragma unroll
            for (int tb = 0; tb < 2; ++tb) {
                int t0 = 2 * tb, t1 = 2 * tb + 1;
                uint4 h4, l4; uint32_t hh, ll;
                split2(acc[m][t0][0], acc[m][t0][1], hh, ll); h4.x = hh; l4.x = ll;
                split2(acc[m][t0][2], acc[m][t0][3], hh, ll); h4.y = hh; l4.y = ll;
                split2(acc[m][t1][0], acc[m][t1][1], hh, ll); h4.z = hh; l4.z = ll;
                split2(acc[m][t1][2], acc[m][t1][3], hh, ll); h4.w = hh; l4.w = ll;
                acc[m][t0][0] = 0.f; acc[m][t0][1] = 0.f; acc[m][t0][2] = 0.f; acc[m][t0][3] = 0.f;
                acc[m][t1][0] = 0.f; acc[m][t1][1] = 0.f; acc[m][t1][2] = 0.f; acc[m][t1][3] = 0.f;
                int kt_out = w * 2 + tb;
                sAhi[(m * 16 + kt_out) * 32 + lane] = h4;
                sAlo[(m * 16 + kt_out) * 32 + lane] = l4;
            }
        }
        __syncthreads();             // new A-frags visible
    }

    // ---------------- stage R/F loads (consumed after L5) --------------------
    float rv[3], fv[3];
    {
        const float* Rg = g_R + (size_t)blockRow * 9;
        const float* Fb = Fg  + (size_t)blockRow * 9;
        #pragma unroll
        for (int i = 0; i < 3; ++i) {
            int idx = tid + i * THREADS;
            bool ok = (idx < 576);
            rv[i] = ok ? __ldg(Rg + idx) : 0.f;
            fv[i] = ok ? __ldg(Fb + idx) : 0.f;
        }
    }

    // ---------------- layer 5: bc holds chunk 50 -----------------------------
    // kt in {2w, 2w+1} via j = 2u + nt
    {
        #pragma unroll
        for (int u = 0; u < 2; ++u) {
            int kt = 2 * w + u;
            #pragma unroll
            for (int m = 0; m < 4; ++m) {
                uint4 ah = sAhi[(m * 16 + kt) * 32 + lane];
                uint4 al = sAlo[(m * 16 + kt) * 32 + lane];
                #pragma unroll
                for (int nt = 0; nt < 2; ++nt) {
                    uint4 b = bc[2 * u + nt];
                    mma_bf16(acc[m][nt], ah, b.x, b.y);
                    mma_bf16(acc[m][nt], al, b.x, b.y);
                    mma_bf16(acc[m][nt], ah, b.z, b.w);
                }
            }
        }
        // store staged R/F (loads have drained under the L5 MMAs)
        float* RF = (float*)(smem + RF_OFF);
        #pragma unroll
        for (int i = 0; i < 3; ++i) {
            int idx = tid + i * THREADS;
            if (idx < 576) { RF[idx] = rv[i]; RF[576 + idx] = fv[i]; }
        }
        // write per-warp partial [64 rows x 16 cols] into scratch
        float* part = (float*)(smem + SCRATCH) + w * 1024;
        #pragma unroll
        for (int m = 0; m < 4; ++m)
            #pragma unroll
            for (int nt = 0; nt < 2; ++nt) {
                int r0 = m * 16 + (lane >> 2);
                int c0 = nt * 8 + 2 * q;
                part[r0 * 16 + c0]           = acc[m][nt][0];
                part[r0 * 16 + c0 + 1]       = acc[m][nt][1];
                part[(r0 + 8) * 16 + c0]     = acc[m][nt][2];
                part[(r0 + 8) * 16 + c0 + 1] = acc[m][nt][3];
            }
    }
    __syncthreads();

    // ---------------- final epilogue: reduce 8 partials, stress --------------
    if (tid < TILE_M) {
        int ig = blockRow + tid;
        if (ig < B) {
            const float* part = (const float*)(smem + SCRATCH);
            const float* RF   = (const float*)(smem + RF_OFF);
            float x[9];
            #pragma unroll
            for (int n = 0; n < 9; ++n) {
                float s = __ldg(b5 + n);
                #pragma unroll
                for (int ww = 0; ww < 8; ++ww)
                    s += part[ww * 1024 + tid * 16 + n];
                x[n] = s;
            }
            float xs[9];
            xs[0]=x[0]; xs[4]=x[4]; xs[8]=x[8];
            xs[1]=xs[3]=0.5f*(x[1]+x[3]);
            xs[2]=xs[6]=0.5f*(x[2]+x[6]);
            xs[5]=xs[7]=0.5f*(x[5]+x[7]);
            float R[9], Ff[9], P[9];
            #pragma unroll
            for (int k = 0; k < 9; ++k) R[k]  = RF[tid * 9 + k];
            #pragma unroll
            for (int k = 0; k < 9; ++k) Ff[k] = RF[576 + tid * 9 + k];
            #pragma unroll
            for (int rI = 0; rI < 3; ++rI)
                #pragma unroll
                for (int cI = 0; cI < 3; ++cI)
                    P[rI*3+cI] = R[rI*3+0]*xs[0*3+cI] + R[rI*3+1]*xs[1*3+cI] + R[rI*3+2]*xs[2*3+cI];
            #pragma unroll
            for (int rI = 0; rI < 3; ++rI)
                #pragma unroll
                for (int cI = 0; cI < 3; ++cI)
                    outg[(size_t)ig*9 + rI*3 + cI] =
                        P[rI*3+0]*Ff[cI*3+0] + P[rI*3+1]*Ff[cI*3+1] + P[rI*3+2]*Ff[cI*3+2];
        }
    }
}

// ---------------- launch ----------------
extern "C" void kernel_launch(void* const* d_in, const int* in_sizes, int n_in,
                              void* d_out, int out_size) {
    const float* F    = (const float*)d_in[0];
    const float* C    = (const float*)d_in[1];
    const float* emb  = (const float*)d_in[2];
    const int*   traj = (const int*)  d_in[3];
    const float* W1 = (const float*)d_in[4];
    const float* b1 = (const float*)d_in[5];
    const float* W2 = (const float*)d_in[6];
    const float* b2 = (const float*)d_in[7];
    const float* W3 = (const float*)d_in[8];
    const float* b3 = (const float*)d_in[9];
    const float* W4 = (const float*)d_in[10];
    const float* b4 = (const float*)d_in[11];
    const float* W5 = (const float*)d_in[12];
    const float* b5 = (const float*)d_in[13];
    float* out = (float*)d_out;

    int B = in_sizes[0] / 9;
    if (B > MAXB) B = MAXB;

    wprep_kernel<<<(26 * 2048 + 255) / 256, 256>>>(W1, W2, W3, W4, W5, emb, traj, b1);

    cudaFuncSetAttribute(mlp_mma_kernel, cudaFuncAttributeMaxDynamicSharedMemorySize, SMEM_TOTAL);
    int nblk = (B + TILE_M - 1) / TILE_M;
    mlp_mma_kernel<<<nblk, THREADS, SMEM_TOTAL>>>(F, C, b2, b3, b4, b5, out, B);
}